// round 1
// baseline (speedup 1.0000x reference)
#include <cuda_runtime.h>
#include <cstdint>

#define B_   2
#define L_   110592
#define C_   64
#define DI_  128
#define T_   64
#define NCH  (L_ / T_)          // 1728
#define EPS_ 1e-3f

// ---------------- scratch (module-load allocated, allowed) ----------------
__device__ float g_u[(size_t)B_ * L_ * DI_];     // 113 MB
__device__ float g_res[(size_t)B_ * L_ * DI_];   // 113 MB
__device__ float g_sums[B_ * NCH * DI_];
__device__ float g_offs[B_ * NCH * DI_];

__device__ __forceinline__ float softplus_f(float v) {
    return (v > 15.f) ? v : log1pf(__expf(v));
}

// =====================================================================
// K1: per 64-token chunk:  x@W_in -> (xs halo, res) ; conv4+silu ;
//     xc@[W_x|W_dt] ; u = xp * softplus(dt) ; chunk channel sums
// smem: s_xin[67*64] | s_xs[67*128] (aliased later by s_dt[64*129]) | s_xc[64*129]
// =====================================================================
__global__ __launch_bounds__(256, 2)
void k1_kernel(const float* __restrict__ x,
               const float* __restrict__ W_in,
               const float* __restrict__ conv_w,
               const float* __restrict__ conv_b,
               const float* __restrict__ W_x,
               const float* __restrict__ W_dt,
               const float* __restrict__ b_dt)
{
    extern __shared__ float smem[];
    float* s_xin = smem;                 // 67*64  = 4288
    float* s_xs  = smem + 4288;          // 67*128 = 8576
    float* s_xc  = smem + 4288 + 8576;   // 64*129 = 8256
    float* s_dt  = s_xs;                 // alias (64*129 = 8256 <= 8576)

    const int bc    = blockIdx.x;
    const int b     = bc / NCH;
    const int chunk = bc - b * NCH;
    const int l0    = chunk * T_;
    const int tid   = threadIdx.x;

    // ---- load x rows l0-1 .. l0+65 (zero outside [0,L)) ----
    for (int i = tid; i < 67 * 16; i += 256) {
        int r = i >> 4, q = i & 15;
        int l = l0 - 1 + r;
        float4 v = make_float4(0.f, 0.f, 0.f, 0.f);
        if (l >= 0 && l < L_)
            v = reinterpret_cast<const float4*>(x + ((size_t)b * L_ + l) * C_)[q];
        reinterpret_cast<float4*>(s_xin)[i] = v;
    }
    __syncthreads();

    // ---- GEMM1: [67 x 64] @ W_in[64 x 256]; col = tid ----
    {
        const int c = tid;
        float w[64];
        #pragma unroll
        for (int k = 0; k < 64; k++) w[k] = W_in[k * 256 + c];

        for (int rt = 0; rt < 67; rt += 8) {
            float acc[8];
            #pragma unroll
            for (int i = 0; i < 8; i++) acc[i] = 0.f;
            #pragma unroll
            for (int i = 0; i < 8; i++) {
                int r = rt + i;
                if (r < 67) {
                    const float4* xr = reinterpret_cast<const float4*>(s_xin + r * 64);
                    float a = 0.f;
                    #pragma unroll
                    for (int q = 0; q < 16; q++) {
                        float4 xv = xr[q];
                        a = fmaf(xv.x, w[4 * q + 0], a);
                        a = fmaf(xv.y, w[4 * q + 1], a);
                        a = fmaf(xv.z, w[4 * q + 2], a);
                        a = fmaf(xv.w, w[4 * q + 3], a);
                    }
                    acc[i] = a;
                }
            }
            #pragma unroll
            for (int i = 0; i < 8; i++) {
                int r = rt + i;
                if (r < 67) {
                    if (c < 128) {
                        s_xs[r * 128 + c] = acc[i];
                    } else if (r >= 1 && r <= 64) {
                        g_res[((size_t)b * L_ + l0 + r - 1) * DI_ + (c - 128)] = acc[i];
                    }
                }
            }
        }
    }
    __syncthreads();

    // ---- depthwise conv (k=4, pad 1/2) + silu -> s_xc[t][c] (stride 129) ----
    {
        const int c = tid & 127, half = tid >> 7;
        const float cw0 = conv_w[0 * 128 + c];
        const float cw1 = conv_w[1 * 128 + c];
        const float cw2 = conv_w[2 * 128 + c];
        const float cw3 = conv_w[3 * 128 + c];
        const float cb  = conv_b[c];
        const int t0 = half * 32;
        float v0 = s_xs[(t0 + 0) * 128 + c];
        float v1 = s_xs[(t0 + 1) * 128 + c];
        float v2 = s_xs[(t0 + 2) * 128 + c];
        #pragma unroll 4
        for (int t = t0; t < t0 + 32; t++) {
            float v3 = s_xs[(t + 3) * 128 + c];
            float z = fmaf(cw0, v0, fmaf(cw1, v1, fmaf(cw2, v2, fmaf(cw3, v3, cb))));
            float sig = 1.f / (1.f + __expf(-z));
            s_xc[t * 129 + c] = z * sig;
            v0 = v1; v1 = v2; v2 = v3;
        }
    }
    __syncthreads();

    // ---- GEMM2: xc[64 x 128] @ [W_x[:, :128] | W_dt] -> xp/dt ----
    // warp = column group (32 cols), lane = row pair {t_r, t_r+32}
    {
        const int t_c = tid >> 5;          // 0..7
        const int t_r = tid & 31;
        const int c0  = t_c * 32;
        const float* Wp;
        int stride, cbase;
        if (t_c < 4) { Wp = W_x;  stride = 144; cbase = c0; }
        else         { Wp = W_dt; stride = 128; cbase = c0 - 128; }

        float acc0[32], acc1[32];
        #pragma unroll
        for (int q = 0; q < 32; q++) { acc0[q] = 0.f; acc1[q] = 0.f; }

        #pragma unroll 2
        for (int k = 0; k < 128; k++) {
            float x0 = s_xc[t_r * 129 + k];
            float x1 = s_xc[(t_r + 32) * 129 + k];
            const float4* wr = reinterpret_cast<const float4*>(Wp + (size_t)k * stride + cbase);
            #pragma unroll
            for (int q4 = 0; q4 < 8; q4++) {
                float4 wv = wr[q4];
                acc0[4*q4+0] = fmaf(x0, wv.x, acc0[4*q4+0]);
                acc0[4*q4+1] = fmaf(x0, wv.y, acc0[4*q4+1]);
                acc0[4*q4+2] = fmaf(x0, wv.z, acc0[4*q4+2]);
                acc0[4*q4+3] = fmaf(x0, wv.w, acc0[4*q4+3]);
                acc1[4*q4+0] = fmaf(x1, wv.x, acc1[4*q4+0]);
                acc1[4*q4+1] = fmaf(x1, wv.y, acc1[4*q4+1]);
                acc1[4*q4+2] = fmaf(x1, wv.z, acc1[4*q4+2]);
                acc1[4*q4+3] = fmaf(x1, wv.w, acc1[4*q4+3]);
            }
        }

        // dt warps: softplus -> s_dt (stride 129, conflict-free across t_r)
        if (t_c >= 4) {
            #pragma unroll 4
            for (int q = 0; q < 32; q++) {
                float bd = b_dt[cbase + q];
                s_dt[t_r * 129 + cbase + q]        = softplus_f(acc0[q] + bd);
                s_dt[(t_r + 32) * 129 + cbase + q] = softplus_f(acc1[q] + bd);
            }
        }
        __syncthreads();

        // xp warps: u = xp * dt ; store + chunk sums
        if (t_c < 4) {
            float u0[32], u1[32];
            #pragma unroll
            for (int q = 0; q < 32; q++) {
                u0[q] = acc0[q] * s_dt[t_r * 129 + c0 + q];
                u1[q] = acc1[q] * s_dt[(t_r + 32) * 129 + c0 + q];
            }
            // stores (float4)
            size_t base0 = ((size_t)b * L_ + l0 + t_r) * DI_ + c0;
            size_t base1 = ((size_t)b * L_ + l0 + t_r + 32) * DI_ + c0;
            #pragma unroll
            for (int q4 = 0; q4 < 8; q4++) {
                reinterpret_cast<float4*>(g_u + base0)[q4] =
                    make_float4(u0[4*q4], u0[4*q4+1], u0[4*q4+2], u0[4*q4+3]);
                reinterpret_cast<float4*>(g_u + base1)[q4] =
                    make_float4(u1[4*q4], u1[4*q4+1], u1[4*q4+2], u1[4*q4+3]);
            }
            // chunk sums: reduce over 64 rows (2 per lane, 32 lanes)
            #pragma unroll
            for (int q = 0; q < 32; q++) {
                float s = u0[q] + u1[q];
                #pragma unroll
                for (int off = 16; off; off >>= 1)
                    s += __shfl_xor_sync(0xffffffffu, s, off);
                if (t_r == 0)
                    g_sums[(b * NCH + chunk) * DI_ + c0 + q] = s;
            }
        }
    }
}

// =====================================================================
// K2: exclusive scan of chunk sums along 1728 chunks per (b, c)
// grid = B*128, block = 64; each thread handles 27 chunks
// =====================================================================
__global__ void k2_scan(void)
{
    const int b = blockIdx.x >> 7;
    const int c = blockIdx.x & 127;
    const int t = threadIdx.x;
    __shared__ float part[64];

    float local[27];
    float s = 0.f;
    #pragma unroll
    for (int i = 0; i < 27; i++) {
        local[i] = g_sums[(b * NCH + t * 27 + i) * DI_ + c];
        s += local[i];
    }
    part[t] = s;
    __syncthreads();
    if (t == 0) {
        float run = 0.f;
        for (int i = 0; i < 64; i++) { float v = part[i]; part[i] = run; run += v; }
    }
    __syncthreads();
    float run = part[t];
    #pragma unroll
    for (int i = 0; i < 27; i++) {
        g_offs[(b * NCH + t * 27 + i) * DI_ + c] = run;
        run += local[i];
    }
}

// =====================================================================
// K3: in-chunk scan -> y = state*silu(res) ; y@W_out ; +x ; LayerNorm
// smem: s_y[64*128] | s_w(float2)[128*32] | s_off[128] | s_mid[128]
// =====================================================================
__global__ __launch_bounds__(256, 2)
void k3_kernel(const float* __restrict__ x,
               const float* __restrict__ W_out,
               const float* __restrict__ gamma,
               const float* __restrict__ beta,
               float* __restrict__ out)
{
    extern __shared__ float smem[];
    float*  s_y   = smem;                        // 8192 floats
    float2* s_w   = reinterpret_cast<float2*>(smem + 8192);  // 4096 float2
    float*  s_off = smem + 8192 + 8192;
    float*  s_mid = s_off + 128;

    const int bc    = blockIdx.x;
    const int b     = bc / NCH;
    const int chunk = bc - b * NCH;
    const int l0    = chunk * T_;
    const int tid   = threadIdx.x;

    // stage W_out pairs (o, o+32)
    for (int i = tid; i < 128 * 32; i += 256) {
        int k = i >> 5, j = i & 31;
        s_w[i] = make_float2(W_out[k * 64 + j], W_out[k * 64 + j + 32]);
    }
    if (tid < 128)
        s_off[tid] = g_offs[(b * NCH + chunk) * DI_ + tid];
    __syncthreads();

    // ---- phase A: split-half in-chunk scan, y into smem ----
    {
        const int c = tid & 127, h = tid >> 7;
        const size_t base = ((size_t)b * L_ + l0 + h * 32) * DI_ + c;
        float uv[32];
        #pragma unroll
        for (int i = 0; i < 32; i++) uv[i] = g_u[base + (size_t)i * DI_];
        float ps = 0.f;
        #pragma unroll
        for (int i = 0; i < 32; i++) ps += uv[i];
        if (h == 0) s_mid[c] = ps;
        __syncthreads();
        float run = s_off[c] + (h ? s_mid[c] : 0.f);
        #pragma unroll 8
        for (int i = 0; i < 32; i++) {
            run += uv[i];
            float r = g_res[base + (size_t)i * DI_];
            float sil = r / (1.f + __expf(-r));
            s_y[(h * 32 + i) * 128 + c] = run * sil;
        }
    }
    __syncthreads();

    // ---- phase B: y @ W_out + x, LayerNorm over 64 ----
    {
        const int w = tid >> 5, lane = tid & 31;
        const float g0 = gamma[lane], g1 = gamma[lane + 32];
        const float be0 = beta[lane], be1 = beta[lane + 32];
        #pragma unroll 1
        for (int tt = 0; tt < 8; tt++) {
            const int t = w * 8 + tt;
            const int l = l0 + t;
            float a0 = 0.f, a1 = 0.f;
            const float4* yr = reinterpret_cast<const float4*>(s_y + t * 128);
            #pragma unroll
            for (int k4 = 0; k4 < 32; k4++) {
                float4 yv = yr[k4];
                float2 w0 = s_w[(4 * k4 + 0) * 32 + lane];
                float2 w1 = s_w[(4 * k4 + 1) * 32 + lane];
                float2 w2 = s_w[(4 * k4 + 2) * 32 + lane];
                float2 w3 = s_w[(4 * k4 + 3) * 32 + lane];
                a0 = fmaf(yv.x, w0.x, a0); a1 = fmaf(yv.x, w0.y, a1);
                a0 = fmaf(yv.y, w1.x, a0); a1 = fmaf(yv.y, w1.y, a1);
                a0 = fmaf(yv.z, w2.x, a0); a1 = fmaf(yv.z, w2.y, a1);
                a0 = fmaf(yv.w, w3.x, a0); a1 = fmaf(yv.w, w3.y, a1);
            }
            const size_t xb = ((size_t)b * L_ + l) * C_;
            float z0 = a0 + x[xb + lane];
            float z1 = a1 + x[xb + lane + 32];
            float s  = z0 + z1;
            float s2 = z0 * z0 + z1 * z1;
            #pragma unroll
            for (int off = 16; off; off >>= 1) {
                s  += __shfl_xor_sync(0xffffffffu, s, off);
                s2 += __shfl_xor_sync(0xffffffffu, s2, off);
            }
            float mu  = s * (1.f / 64.f);
            float var = s2 * (1.f / 64.f) - mu * mu;
            float inv = rsqrtf(var + EPS_);
            out[xb + lane]      = fmaf(g0, (z0 - mu) * inv, be0);
            out[xb + lane + 32] = fmaf(g1, (z1 - mu) * inv, be1);
        }
    }
}

// =====================================================================
extern "C" void kernel_launch(void* const* d_in, const int* in_sizes, int n_in,
                              void* d_out, int out_size)
{
    (void)in_sizes; (void)n_in; (void)out_size;
    const float* x      = (const float*)d_in[0];
    const float* W_in   = (const float*)d_in[1];
    const float* conv_w = (const float*)d_in[2];
    const float* conv_b = (const float*)d_in[3];
    const float* W_x    = (const float*)d_in[4];
    const float* W_dt   = (const float*)d_in[5];
    const float* b_dt   = (const float*)d_in[6];
    const float* W_out  = (const float*)d_in[7];
    const float* gamma  = (const float*)d_in[8];
    const float* beta   = (const float*)d_in[9];
    float* out = (float*)d_out;

    const int smem1 = (4288 + 8576 + 8256) * 4;          // 84480 B
    const int smem3 = (8192 + 8192 + 128 + 128) * 4;     // 66560 B
    cudaFuncSetAttribute(k1_kernel, cudaFuncAttributeMaxDynamicSharedMemorySize, smem1);
    cudaFuncSetAttribute(k3_kernel, cudaFuncAttributeMaxDynamicSharedMemorySize, smem3);

    k1_kernel<<<B_ * NCH, 256, smem1>>>(x, W_in, conv_w, conv_b, W_x, W_dt, b_dt);
    k2_scan<<<B_ * 128, 64>>>();
    k3_kernel<<<B_ * NCH, 256, smem3>>>(x, W_out, gamma, beta, out);
}

// round 2
// speedup vs baseline: 2.1412x; 2.1412x over previous
#include <cuda_runtime.h>
#include <cstdint>

typedef unsigned long long ull;

#define B_   2
#define L_   110592
#define C_   64
#define DI_  128
#define NCH  1728
#define EPS_ 1e-3f

// ---- K1 smem layout (floats) ----
#define S_XIN 0            // 67*64  = 4288
#define S_XS  4288         // 67*128 = 8576
#define S_XCT 12864        // 128*68 = 8704
#define K1_SMEM_FLOATS 21568
// ---- K3 smem layout (floats) ----
#define S3_YT   0          // 128*68 = 8704
#define S3_W2   8704       // 128*32 ull = 8192 floats
#define S3_OFF  16896      // 128
#define S3_MID  17024      // 128
#define K3_SMEM_FLOATS 17152

__device__ float g_u[(size_t)B_ * L_ * DI_];
__device__ float g_res[(size_t)B_ * L_ * DI_];   // holds silu(res)
__device__ float g_sums[B_ * NCH * DI_];
__device__ float g_offs[B_ * NCH * DI_];

__device__ __forceinline__ ull ffma2(ull a, ull b, ull c) {
    ull d; asm("fma.rn.f32x2 %0, %1, %2, %3;" : "=l"(d) : "l"(a), "l"(b), "l"(c)); return d;
}
__device__ __forceinline__ ull pack2(float lo, float hi) {
    ull d; asm("mov.b64 %0, {%1, %2};" : "=l"(d) : "f"(lo), "f"(hi)); return d;
}
__device__ __forceinline__ ull dup2(float v) {
    ull d; asm("mov.b64 %0, {%1, %1};" : "=l"(d) : "f"(v)); return d;
}
__device__ __forceinline__ float2 unpack2(ull p) {
    float lo, hi; asm("mov.b64 {%0, %1}, %2;" : "=f"(lo), "=f"(hi) : "l"(p));
    return make_float2(lo, hi);
}
__device__ __forceinline__ float softplus_f(float v) {
    return (v > 15.f) ? v : log1pf(__expf(v));
}

// =====================================================================
// K1: x@W_in (halo) -> xs,silu-res ; conv4+silu -> s_xcT ;
//     xc@[W_x|W_dt] (smem-staged, f32x2 8x8 tiles) ; u = xp*softplus(dt)
// =====================================================================
__global__ __launch_bounds__(256, 2)
void k1_kernel(const float* __restrict__ x,
               const float* __restrict__ W_in,
               const float* __restrict__ conv_w,
               const float* __restrict__ conv_b,
               const float* __restrict__ W_x,
               const float* __restrict__ W_dt,
               const float* __restrict__ b_dt)
{
    extern __shared__ float smem[];
    float* s_xin = smem + S_XIN;
    float* s_xs  = smem + S_XS;
    float* s_xcT = smem + S_XCT;
    float* s_B   = smem + S_XIN;   // alias: dead after GEMM1
    float* s_part= smem + S_XS;    // alias: dead after conv

    const int bc    = blockIdx.x;
    const int b     = bc / NCH;
    const int chunk = bc - b * NCH;
    const int l0    = chunk * 64;
    const int tid   = threadIdx.x;

    // ---- load x rows l0-1 .. l0+65 ----
    for (int i = tid; i < 67 * 16; i += 256) {
        int r = i >> 4, q = i & 15;
        int l = l0 - 1 + r;
        float4 v = make_float4(0.f, 0.f, 0.f, 0.f);
        if (l >= 0 && l < L_)
            v = reinterpret_cast<const float4*>(x + ((size_t)b * L_ + l) * C_)[q];
        reinterpret_cast<float4*>(s_xin)[i] = v;
    }
    __syncthreads();

    // ---- GEMM1: [67 x 64] @ W_in[64 x 256], f32x2 over k-pairs ----
    {
        const int c = tid;
        ull w2[32];
        #pragma unroll
        for (int j = 0; j < 32; j++)
            w2[j] = pack2(W_in[(size_t)(2 * j) * 256 + c],
                          W_in[(size_t)(2 * j + 1) * 256 + c]);

        for (int rt = 0; rt < 67; rt += 8) {
            #pragma unroll
            for (int i = 0; i < 8; i++) {
                int r = rt + i;
                if (r < 67) {
                    const float4* xr = reinterpret_cast<const float4*>(s_xin + r * 64);
                    ull a = 0ull;
                    #pragma unroll
                    for (int q = 0; q < 16; q++) {
                        float4 xv = xr[q];
                        a = ffma2(pack2(xv.x, xv.y), w2[2 * q],     a);
                        a = ffma2(pack2(xv.z, xv.w), w2[2 * q + 1], a);
                    }
                    float2 hv = unpack2(a);
                    float v = hv.x + hv.y;
                    if (c < 128) {
                        s_xs[r * 128 + c] = v;
                    } else if (r >= 1 && r <= 64) {
                        float sil = v / (1.f + __expf(-v));
                        g_res[((size_t)b * L_ + l0 + r - 1) * DI_ + (c - 128)] = sil;
                    }
                }
            }
        }
    }
    __syncthreads();

    // ---- conv k=4 + silu -> s_xcT[c][t] (stride 68, float4 stores) ----
    {
        const int cch = tid & 127, half = tid >> 7;
        const float cw0 = conv_w[0 * 128 + cch];
        const float cw1 = conv_w[1 * 128 + cch];
        const float cw2 = conv_w[2 * 128 + cch];
        const float cw3 = conv_w[3 * 128 + cch];
        const float cb  = conv_b[cch];
        const int t0 = half * 32;
        float v0 = s_xs[(t0 + 0) * 128 + cch];
        float v1 = s_xs[(t0 + 1) * 128 + cch];
        float v2 = s_xs[(t0 + 2) * 128 + cch];
        float bufv[4];
        #pragma unroll
        for (int i = 0; i < 32; i++) {
            int t = t0 + i;
            float v3 = s_xs[(t + 3) * 128 + cch];
            float z = fmaf(cw0, v0, fmaf(cw1, v1, fmaf(cw2, v2, fmaf(cw3, v3, cb))));
            float sig = 1.f / (1.f + __expf(-z));
            bufv[i & 3] = z * sig;
            if ((i & 3) == 3)
                *reinterpret_cast<float4*>(s_xcT + cch * 68 + t - 3) =
                    make_float4(bufv[0], bufv[1], bufv[2], bufv[3]);
            v0 = v1; v1 = v2; v2 = v3;
        }
    }

    // ---- GEMM2: xc[64x128] @ [W_x|W_dt][128x256], K-sliced smem staging ----
    {
        const int w    = tid >> 5;
        const int lane = tid & 31;
        ull acc[8][4];
        #pragma unroll
        for (int r = 0; r < 8; r++)
            #pragma unroll
            for (int j = 0; j < 4; j++) acc[r][j] = 0ull;

        for (int s = 0; s < 8; s++) {
            __syncthreads();   // protect s_B (and first: end of conv)
            #pragma unroll
            for (int q = 0; q < 4; q++) {
                int f  = tid + 256 * q;         // float4 index 0..1023
                int kk = f >> 6;
                int c4 = (f & 63) << 2;
                int k  = 16 * s + kk;
                float4 v = (c4 < 128)
                    ? *reinterpret_cast<const float4*>(W_x  + (size_t)k * 144 + c4)
                    : *reinterpret_cast<const float4*>(W_dt + (size_t)k * 128 + (c4 - 128));
                *reinterpret_cast<float4*>(s_B + kk * 256 + c4) = v;
            }
            __syncthreads();

            #pragma unroll 4
            for (int kk = 0; kk < 16; kk++) {
                const float* aT = s_xcT + (16 * s + kk) * 68 + 8 * w;
                float4 A0 = *reinterpret_cast<const float4*>(aT);
                float4 A1 = *reinterpret_cast<const float4*>(aT + 4);
                const float* bp = s_B + kk * 256 + 4 * lane;
                float4 B0 = *reinterpret_cast<const float4*>(bp);        // xp cols
                float4 B1 = *reinterpret_cast<const float4*>(bp + 128);  // dt cols
                ull b0 = pack2(B0.x, B0.y), b1 = pack2(B0.z, B0.w);
                ull b2 = pack2(B1.x, B1.y), b3 = pack2(B1.z, B1.w);
                float av[8] = {A0.x, A0.y, A0.z, A0.w, A1.x, A1.y, A1.z, A1.w};
                #pragma unroll
                for (int r = 0; r < 8; r++) {
                    ull ar = dup2(av[r]);
                    acc[r][0] = ffma2(ar, b0, acc[r][0]);
                    acc[r][1] = ffma2(ar, b1, acc[r][1]);
                    acc[r][2] = ffma2(ar, b2, acc[r][2]);
                    acc[r][3] = ffma2(ar, b3, acc[r][3]);
                }
            }
        }

        // ---- epilogue: u = xp * softplus(dt + b_dt), coalesced stores ----
        float4 bdv = *reinterpret_cast<const float4*>(b_dt + 4 * lane);
        float ps0 = 0.f, ps1 = 0.f, ps2 = 0.f, ps3 = 0.f;
        const size_t rowbase = ((size_t)b * L_ + l0 + 8 * w) * DI_ + 4 * lane;
        #pragma unroll
        for (int r = 0; r < 8; r++) {
            float2 xp0 = unpack2(acc[r][0]);
            float2 xp1 = unpack2(acc[r][1]);
            float2 dt0 = unpack2(acc[r][2]);
            float2 dt1 = unpack2(acc[r][3]);
            float u0 = xp0.x * softplus_f(dt0.x + bdv.x);
            float u1 = xp0.y * softplus_f(dt0.y + bdv.y);
            float u2 = xp1.x * softplus_f(dt1.x + bdv.z);
            float u3 = xp1.y * softplus_f(dt1.y + bdv.w);
            *reinterpret_cast<float4*>(g_u + rowbase + (size_t)r * DI_) =
                make_float4(u0, u1, u2, u3);
            ps0 += u0; ps1 += u1; ps2 += u2; ps3 += u3;
        }
        *reinterpret_cast<float4*>(s_part + w * 128 + 4 * lane) =
            make_float4(ps0, ps1, ps2, ps3);
        __syncthreads();
        if (tid < 128) {
            float s = 0.f;
            #pragma unroll
            for (int j = 0; j < 8; j++) s += s_part[j * 128 + tid];
            g_sums[(b * NCH + chunk) * DI_ + tid] = s;
        }
    }
}

// =====================================================================
// K2: exclusive scan of chunk sums
// =====================================================================
__global__ void k2_scan(void)
{
    const int b = blockIdx.x >> 7;
    const int c = blockIdx.x & 127;
    const int t = threadIdx.x;
    __shared__ float part[64];

    float local[27];
    float s = 0.f;
    #pragma unroll
    for (int i = 0; i < 27; i++) {
        local[i] = g_sums[(b * NCH + t * 27 + i) * DI_ + c];
        s += local[i];
    }
    part[t] = s;
    __syncthreads();
    if (t == 0) {
        float run = 0.f;
        for (int i = 0; i < 64; i++) { float v = part[i]; part[i] = run; run += v; }
    }
    __syncthreads();
    float run = part[t];
    #pragma unroll
    for (int i = 0; i < 27; i++) {
        g_offs[(b * NCH + t * 27 + i) * DI_ + c] = run;
        run += local[i];
    }
}

// =====================================================================
// K3: in-chunk scan -> y (transposed smem) ; y@W_out (f32x2) ; +x ; LN
// =====================================================================
__global__ __launch_bounds__(256, 3)
void k3_kernel(const float* __restrict__ x,
               const float* __restrict__ W_out,
               const float* __restrict__ gamma,
               const float* __restrict__ beta,
               float* __restrict__ out)
{
    extern __shared__ float smem[];
    float* s_yT  = smem + S3_YT;                           // [k][t] stride 68
    ull*   s_w2  = reinterpret_cast<ull*>(smem + S3_W2);   // [k][lane] pairs
    float* s_off = smem + S3_OFF;
    float* s_mid = smem + S3_MID;

    const int bc    = blockIdx.x;
    const int b     = bc / NCH;
    const int chunk = bc - b * NCH;
    const int l0    = chunk * 64;
    const int tid   = threadIdx.x;

    // stage W_out pairs (o, o+32)
    for (int i = tid; i < 128 * 32; i += 256) {
        int k = i >> 5, j = i & 31;
        s_w2[i] = pack2(W_out[k * 64 + j], W_out[k * 64 + j + 32]);
    }
    if (tid < 128)
        s_off[tid] = g_offs[(b * NCH + chunk) * DI_ + tid];
    __syncthreads();

    // ---- phase A: split-half scan, y -> s_yT (transposed) ----
    {
        const int c = tid & 127, h = tid >> 7;
        const size_t base = ((size_t)b * L_ + l0 + h * 32) * DI_ + c;
        float uv[32];
        #pragma unroll
        for (int i = 0; i < 32; i++) uv[i] = g_u[base + (size_t)i * DI_];
        float ps = 0.f;
        #pragma unroll
        for (int i = 0; i < 32; i++) ps += uv[i];
        if (h == 0) s_mid[c] = ps;
        __syncthreads();
        float run = s_off[c] + (h ? s_mid[c] : 0.f);
        float bufv[4];
        #pragma unroll
        for (int i = 0; i < 32; i++) {
            run += uv[i];
            float r = g_res[base + (size_t)i * DI_];   // silu already applied
            bufv[i & 3] = run * r;
            if ((i & 3) == 3)
                *reinterpret_cast<float4*>(s_yT + c * 68 + h * 32 + i - 3) =
                    make_float4(bufv[0], bufv[1], bufv[2], bufv[3]);
        }
    }
    __syncthreads();

    // ---- phase B: y @ W_out (+x, LayerNorm), f32x2 row-pairs ----
    {
        const int w = tid >> 5, lane = tid & 31;
        ull acc[4][2];
        #pragma unroll
        for (int rp = 0; rp < 4; rp++) { acc[rp][0] = 0ull; acc[rp][1] = 0ull; }

        #pragma unroll 4
        for (int k = 0; k < 128; k++) {
            const float* yp = s_yT + k * 68 + 8 * w;
            float4 Y0 = *reinterpret_cast<const float4*>(yp);
            float4 Y1 = *reinterpret_cast<const float4*>(yp + 4);
            float2 wf = unpack2(s_w2[k * 32 + lane]);
            ull w0 = dup2(wf.x), w1 = dup2(wf.y);
            ull y0 = pack2(Y0.x, Y0.y), y1 = pack2(Y0.z, Y0.w);
            ull y2 = pack2(Y1.x, Y1.y), y3 = pack2(Y1.z, Y1.w);
            acc[0][0] = ffma2(y0, w0, acc[0][0]); acc[0][1] = ffma2(y0, w1, acc[0][1]);
            acc[1][0] = ffma2(y1, w0, acc[1][0]); acc[1][1] = ffma2(y1, w1, acc[1][1]);
            acc[2][0] = ffma2(y2, w0, acc[2][0]); acc[2][1] = ffma2(y2, w1, acc[2][1]);
            acc[3][0] = ffma2(y3, w0, acc[3][0]); acc[3][1] = ffma2(y3, w1, acc[3][1]);
        }

        const float g0 = gamma[lane],  g1 = gamma[lane + 32];
        const float be0 = beta[lane],  be1 = beta[lane + 32];
        #pragma unroll
        for (int rp = 0; rp < 4; rp++) {
            float2 zc0 = unpack2(acc[rp][0]);   // rows (2rp, 2rp+1) at col lane
            float2 zc1 = unpack2(acc[rp][1]);   // rows (2rp, 2rp+1) at col lane+32
            #pragma unroll
            for (int rr = 0; rr < 2; rr++) {
                const int l = l0 + 8 * w + 2 * rp + rr;
                const size_t xb = ((size_t)b * L_ + l) * C_;
                float z0 = (rr ? zc0.y : zc0.x) + x[xb + lane];
                float z1 = (rr ? zc1.y : zc1.x) + x[xb + lane + 32];
                float s  = z0 + z1;
                float s2 = z0 * z0 + z1 * z1;
                #pragma unroll
                for (int off = 16; off; off >>= 1) {
                    s  += __shfl_xor_sync(0xffffffffu, s,  off);
                    s2 += __shfl_xor_sync(0xffffffffu, s2, off);
                }
                float mu  = s * (1.f / 64.f);
                float var = s2 * (1.f / 64.f) - mu * mu;
                float inv = rsqrtf(var + EPS_);
                out[xb + lane]      = fmaf(g0, (z0 - mu) * inv, be0);
                out[xb + lane + 32] = fmaf(g1, (z1 - mu) * inv, be1);
            }
        }
    }
}

// =====================================================================
extern "C" void kernel_launch(void* const* d_in, const int* in_sizes, int n_in,
                              void* d_out, int out_size)
{
    (void)in_sizes; (void)n_in; (void)out_size;
    const float* x      = (const float*)d_in[0];
    const float* W_in   = (const float*)d_in[1];
    const float* conv_w = (const float*)d_in[2];
    const float* conv_b = (const float*)d_in[3];
    const float* W_x    = (const float*)d_in[4];
    const float* W_dt   = (const float*)d_in[5];
    const float* b_dt   = (const float*)d_in[6];
    const float* W_out  = (const float*)d_in[7];
    const float* gamma  = (const float*)d_in[8];
    const float* beta   = (const float*)d_in[9];
    float* out = (float*)d_out;

    const int smem1 = K1_SMEM_FLOATS * 4;   // 86272 B
    const int smem3 = K3_SMEM_FLOATS * 4;   // 68608 B
    cudaFuncSetAttribute(k1_kernel, cudaFuncAttributeMaxDynamicSharedMemorySize, smem1);
    cudaFuncSetAttribute(k3_kernel, cudaFuncAttributeMaxDynamicSharedMemorySize, smem3);

    k1_kernel<<<B_ * NCH, 256, smem1>>>(x, W_in, conv_w, conv_b, W_x, W_dt, b_dt);
    k2_scan<<<B_ * 128, 64>>>();
    k3_kernel<<<B_ * NCH, 256, smem3>>>(x, W_out, gamma, beta, out);
}

// round 4
// speedup vs baseline: 2.4616x; 1.1496x over previous
#include <cuda_runtime.h>
#include <cuda_bf16.h>
#include <cstdint>

typedef unsigned long long ull;
typedef unsigned int u32;
typedef unsigned short u16;

#define B_   2
#define L_   110592
#define C_   64
#define DI_  128
#define NCH  1728               // 64-token chunks per batch
#define NTIL (B_ * NCH)         // 3456 tiles (64 tokens each)
#define EPS_ 1e-3f

// ---- k1a smem layout (floats) ----
#define S_XIN 0                 // 67*64  = 4288
#define S_XS  4288              // 67*128 = 8576
#define S_IMG 12864             // 32KB bf16 images (hi 16KB + lo 16KB) = 8192 floats
#define K1_SMEM_FLOATS 21056
// ---- K3 smem layout (floats) ----
#define S3_YT   0
#define S3_W2   8704
#define S3_OFF  16896
#define S3_MID  17024
#define K3_SMEM_FLOATS 17152
// ---- kb smem layout (bytes) ----
#define KB_BH   0               // 64KB
#define KB_BL   65536           // 64KB
#define KB_A    131072          // 2 bufs x (hi 16KB + lo 16KB)
#define KB_BDT  196608          // 512B
#define KB_SUMS 197120          // 512B
#define KB_SMEM 197632

// ---------------- global scratch ----------------
__device__ float g_u[(size_t)B_ * L_ * DI_];
__device__ float g_res[(size_t)B_ * L_ * DI_];   // silu(res)
__device__ float g_sums[NTIL * DI_];
__device__ float g_offs[NTIL * DI_];
__device__ uint4 g_xch4[(size_t)NTIL * 1024];    // xc hi chunk images (16KB each)
__device__ uint4 g_xcl4[(size_t)NTIL * 1024];    // xc lo
__device__ uint4 g_Bh4[4096];                    // W2 hi image [128k][256n] bf16
__device__ uint4 g_Bl4[4096];                    // W2 lo

// ---------------- helpers ----------------
__device__ __forceinline__ ull ffma2(ull a, ull b, ull c) {
    ull d; asm("fma.rn.f32x2 %0, %1, %2, %3;" : "=l"(d) : "l"(a), "l"(b), "l"(c)); return d;
}
__device__ __forceinline__ ull pack2(float lo, float hi) {
    ull d; asm("mov.b64 %0, {%1, %2};" : "=l"(d) : "f"(lo), "f"(hi)); return d;
}
__device__ __forceinline__ float2 unpack2(ull p) {
    float lo, hi; asm("mov.b64 {%0, %1}, %2;" : "=f"(lo), "=f"(hi) : "l"(p));
    return make_float2(lo, hi);
}
__device__ __forceinline__ float softplus_f(float v) {
    return (v > 15.f) ? v : log1pf(__expf(v));
}
__device__ __forceinline__ u32 smem_u32(const void* p) {
    u32 a; asm("{ .reg .u64 t; cvta.to.shared.u64 t, %1; cvt.u32.u64 %0, t; }"
               : "=r"(a) : "l"(p));
    return a;
}
__device__ __forceinline__ void mma_bf16(float& d0, float& d1, float& d2, float& d3,
                                         u32 a0, u32 a1, u32 a2, u32 a3,
                                         u32 b0, u32 b1) {
    asm volatile("mma.sync.aligned.m16n8k16.row.col.f32.bf16.bf16.f32 "
                 "{%0,%1,%2,%3}, {%4,%5,%6,%7}, {%8,%9}, {%0,%1,%2,%3};"
                 : "+f"(d0), "+f"(d1), "+f"(d2), "+f"(d3)
                 : "r"(a0), "r"(a1), "r"(a2), "r"(a3), "r"(b0), "r"(b1));
}
__device__ __forceinline__ void ldmatrix_x4(u32& r0, u32& r1, u32& r2, u32& r3, u32 addr) {
    asm volatile("ldmatrix.sync.aligned.m8n8.x4.shared.b16 {%0,%1,%2,%3}, [%4];"
                 : "=r"(r0), "=r"(r1), "=r"(r2), "=r"(r3) : "r"(addr));
}
__device__ __forceinline__ void ldmatrix_x2t(u32& r0, u32& r1, u32 addr) {
    asm volatile("ldmatrix.sync.aligned.m8n8.x2.trans.shared.b16 {%0,%1}, [%2];"
                 : "=r"(r0), "=r"(r1) : "r"(addr));
}
#define CP_ASYNC16(dst, src) \
    asm volatile("cp.async.cg.shared.global [%0], [%1], 16;" :: "r"(dst), "l"(src))
#define CP_COMMIT() asm volatile("cp.async.commit_group;")
#define CP_WAIT(n)  asm volatile("cp.async.wait_group %0;" :: "n"(n))

// A image: token t (0..63), channel c (0..127):
//   byte = t*256 + (((c>>3) ^ (t&7))<<4) + (c&7)*2
// B image: k (0..127), n (0..255):
//   byte = k*512 + ((((n>>3) ^ (k&7)))<<4) + (n&7)*2

// =====================================================================
// k_prep: fused [W_x[:, :128] | W_dt] -> bf16 hi/lo swizzled images
// =====================================================================
__global__ void k_prep(const float* __restrict__ W_x,
                       const float* __restrict__ W_dt)
{
    u16* bh = reinterpret_cast<u16*>(g_Bh4);
    u16* bl = reinterpret_cast<u16*>(g_Bl4);
    int idx = blockIdx.x * 256 + threadIdx.x;
    for (int i = idx; i < 128 * 256; i += gridDim.x * 256) {
        int k = i >> 8, n = i & 255;
        float w = (n < 128) ? W_x[(size_t)k * 144 + n] : W_dt[(size_t)k * 128 + (n - 128)];
        __nv_bfloat16 hi = __float2bfloat16(w);
        __nv_bfloat16 lo = __float2bfloat16(w - __bfloat162float(hi));
        u32 off = (u32)k * 512 + ((((n >> 3) ^ (k & 7))) << 4) + (n & 7) * 2;
        bh[off >> 1] = *reinterpret_cast<u16*>(&hi);
        bl[off >> 1] = *reinterpret_cast<u16*>(&lo);
    }
}

// =====================================================================
// k1a: x@W_in (halo, f32x2) -> xs, silu(res) ; conv4+silu -> bf16 hi/lo
//      swizzled chunk images -> global
// =====================================================================
__global__ __launch_bounds__(256, 2)
void k1a_kernel(const float* __restrict__ x,
                const float* __restrict__ W_in,
                const float* __restrict__ conv_w,
                const float* __restrict__ conv_b)
{
    extern __shared__ float smem[];
    float* s_xin = smem + S_XIN;
    float* s_xs  = smem + S_XS;
    u16*   imgh  = reinterpret_cast<u16*>(smem + S_IMG);   // 16KB
    u16*   imgl  = imgh + 8192;                            // 16KB

    const int bc    = blockIdx.x;                          // == tile index
    const int b     = bc / NCH;
    const int chunk = bc - b * NCH;
    const int l0    = chunk * 64;
    const int tid   = threadIdx.x;

    for (int i = tid; i < 67 * 16; i += 256) {
        int r = i >> 4, q = i & 15;
        int l = l0 - 1 + r;
        float4 v = make_float4(0.f, 0.f, 0.f, 0.f);
        if (l >= 0 && l < L_)
            v = reinterpret_cast<const float4*>(x + ((size_t)b * L_ + l) * C_)[q];
        reinterpret_cast<float4*>(s_xin)[i] = v;
    }
    __syncthreads();

    // GEMM1: [67 x 64] @ W_in[64 x 256]
    {
        const int c = tid;
        ull w2[32];
        #pragma unroll
        for (int j = 0; j < 32; j++)
            w2[j] = pack2(W_in[(size_t)(2 * j) * 256 + c],
                          W_in[(size_t)(2 * j + 1) * 256 + c]);

        for (int rt = 0; rt < 67; rt += 8) {
            #pragma unroll
            for (int i = 0; i < 8; i++) {
                int r = rt + i;
                if (r < 67) {
                    const float4* xr = reinterpret_cast<const float4*>(s_xin + r * 64);
                    ull a = 0ull;
                    #pragma unroll
                    for (int q = 0; q < 16; q++) {
                        float4 xv = xr[q];
                        a = ffma2(pack2(xv.x, xv.y), w2[2 * q],     a);
                        a = ffma2(pack2(xv.z, xv.w), w2[2 * q + 1], a);
                    }
                    float2 hv = unpack2(a);
                    float v = hv.x + hv.y;
                    if (c < 128) {
                        s_xs[r * 128 + c] = v;
                    } else if (r >= 1 && r <= 64) {
                        float sil = v / (1.f + __expf(-v));
                        g_res[((size_t)b * L_ + l0 + r - 1) * DI_ + (c - 128)] = sil;
                    }
                }
            }
        }
    }
    __syncthreads();

    // conv k=4 + silu -> bf16 hi/lo into swizzled image
    {
        const int cch = tid & 127, half = tid >> 7;
        const float cw0 = conv_w[0 * 128 + cch];
        const float cw1 = conv_w[1 * 128 + cch];
        const float cw2 = conv_w[2 * 128 + cch];
        const float cw3 = conv_w[3 * 128 + cch];
        const float cb  = conv_b[cch];
        const int t0 = half * 32;
        float v0 = s_xs[(t0 + 0) * 128 + cch];
        float v1 = s_xs[(t0 + 1) * 128 + cch];
        float v2 = s_xs[(t0 + 2) * 128 + cch];
        #pragma unroll 4
        for (int t = t0; t < t0 + 32; t++) {
            float v3 = s_xs[(t + 3) * 128 + cch];
            float z = fmaf(cw0, v0, fmaf(cw1, v1, fmaf(cw2, v2, fmaf(cw3, v3, cb))));
            float sig = 1.f / (1.f + __expf(-z));
            float v = z * sig;
            __nv_bfloat16 hi = __float2bfloat16(v);
            __nv_bfloat16 lo = __float2bfloat16(v - __bfloat162float(hi));
            u32 off = (u32)t * 256 + ((((cch >> 3) ^ (t & 7))) << 4) + (cch & 7) * 2;
            imgh[off >> 1] = *reinterpret_cast<u16*>(&hi);
            imgl[off >> 1] = *reinterpret_cast<u16*>(&lo);
            v0 = v1; v1 = v2; v2 = v3;
        }
    }
    __syncthreads();

    {
        const uint4* sh = reinterpret_cast<const uint4*>(imgh);
        const uint4* sl = reinterpret_cast<const uint4*>(imgl);
        for (int i = tid; i < 1024; i += 256) {
            g_xch4[(size_t)bc * 1024 + i] = sh[i];
            g_xcl4[(size_t)bc * 1024 + i] = sl[i];
        }
    }
}

// =====================================================================
// kb: persistent tensor-core GEMM2 via mma.sync bf16 (3-term split)
//     per tile (64 tokens): xc[64x128] @ W2[128x256] ->
//     u = xp * softplus(dt + b_dt) ; chunk sums
// =====================================================================
__global__ __launch_bounds__(256, 1)
void kb_kernel(const float* __restrict__ b_dt)
{
    extern __shared__ char sm[];
    const u32 smb = smem_u32(sm);
    float* s_bdt  = reinterpret_cast<float*>(sm + KB_BDT);
    float* s_sums = reinterpret_cast<float*>(sm + KB_SUMS);

    const int tid  = threadIdx.x;
    const int w    = tid >> 5;
    const int lane = tid & 31;
    const int wm   = w >> 2;        // 0..1 : M rows [wm*32, +32)
    const int wn   = w & 3;         // 0..3 : xp cols [wn*32, +32), dt cols +128

    // stage B (hi/lo, 64KB each) once
    {
        uint4* dh = reinterpret_cast<uint4*>(sm + KB_BH);
        uint4* dl = reinterpret_cast<uint4*>(sm + KB_BL);
        for (int i = tid; i < 4096; i += 256) { dh[i] = g_Bh4[i]; dl[i] = g_Bl4[i]; }
    }
    if (tid < 128) s_bdt[tid] = b_dt[tid];
    if (tid < 128) s_sums[tid] = 0.f;

    // prefetch first A tile into buf 0
    int tile0 = blockIdx.x;
    if (tile0 < NTIL) {
        u32 dh = smb + KB_A;
        const char* srcH = reinterpret_cast<const char*>(g_xch4 + (size_t)tile0 * 1024);
        const char* srcL = reinterpret_cast<const char*>(g_xcl4 + (size_t)tile0 * 1024);
        for (int i = tid; i < 1024; i += 256) {
            CP_ASYNC16(dh + i * 16,         srcH + i * 16);
            CP_ASYNC16(dh + 16384 + i * 16, srcL + i * 16);
        }
    }
    CP_COMMIT();

    int it = 0;
    for (int tile = tile0; tile < NTIL; tile += gridDim.x, it++) {
        const int buf = it & 1;
        const int nxt = tile + gridDim.x;
        if (nxt < NTIL) {
            u32 dh = smb + KB_A + (buf ^ 1) * 32768;
            const char* srcH = reinterpret_cast<const char*>(g_xch4 + (size_t)nxt * 1024);
            const char* srcL = reinterpret_cast<const char*>(g_xcl4 + (size_t)nxt * 1024);
            for (int i = tid; i < 1024; i += 256) {
                CP_ASYNC16(dh + i * 16,         srcH + i * 16);
                CP_ASYNC16(dh + 16384 + i * 16, srcL + i * 16);
            }
            CP_COMMIT();
            CP_WAIT(1);
        } else {
            CP_WAIT(0);
        }
        __syncthreads();    // A[buf] ready, s_sums zeroed

        const u32 aH = smb + KB_A + buf * 32768;
        const u32 aL = aH + 16384;
        const u32 bH = smb + KB_BH;
        const u32 bL = smb + KB_BL;

        float acc[2][8][4];
        #pragma unroll
        for (int mf = 0; mf < 2; mf++)
            #pragma unroll
            for (int nf = 0; nf < 8; nf++)
                #pragma unroll
                for (int j = 0; j < 4; j++) acc[mf][nf][j] = 0.f;

        #pragma unroll 1
        for (int ks = 0; ks < 8; ks++) {
            u32 ah[2][4], al[2][4];
            #pragma unroll
            for (int mf = 0; mf < 2; mf++) {
                int row = wm * 32 + mf * 16 + (lane & 15);
                int chunk = ks * 2 + (lane >> 4);
                u32 off = (u32)row * 256 + (((chunk ^ (row & 7))) << 4);
                ldmatrix_x4(ah[mf][0], ah[mf][1], ah[mf][2], ah[mf][3], aH + off);
                ldmatrix_x4(al[mf][0], al[mf][1], al[mf][2], al[mf][3], aL + off);
            }
            int krow = ks * 16 + (lane & 15);
            u32 krbase = (u32)krow * 512;
            int kx = krow & 7;
            #pragma unroll
            for (int nfi = 0; nfi < 8; nfi++) {
                int n0 = (nfi < 4) ? (wn * 32 + nfi * 8) : (128 + wn * 32 + (nfi - 4) * 8);
                u32 off = krbase + ((((n0 >> 3) ^ kx)) << 4);
                u32 bh0, bh1, bl0, bl1;
                ldmatrix_x2t(bh0, bh1, bH + off);
                ldmatrix_x2t(bl0, bl1, bL + off);
                #pragma unroll
                for (int mf = 0; mf < 2; mf++) {
                    mma_bf16(acc[mf][nfi][0], acc[mf][nfi][1], acc[mf][nfi][2], acc[mf][nfi][3],
                             ah[mf][0], ah[mf][1], ah[mf][2], ah[mf][3], bh0, bh1);
                    mma_bf16(acc[mf][nfi][0], acc[mf][nfi][1], acc[mf][nfi][2], acc[mf][nfi][3],
                             ah[mf][0], ah[mf][1], ah[mf][2], ah[mf][3], bl0, bl1);
                    mma_bf16(acc[mf][nfi][0], acc[mf][nfi][1], acc[mf][nfi][2], acc[mf][nfi][3],
                             al[mf][0], al[mf][1], al[mf][2], al[mf][3], bh0, bh1);
                }
            }
        }

        // epilogue: pair xp (nfi) with dt (nfi+4)
        #pragma unroll
        for (int mf = 0; mf < 2; mf++) {
            const int r0 = wm * 32 + mf * 16 + (lane >> 2);
            const size_t tok0 = (size_t)tile * 64 + r0;
            #pragma unroll
            for (int nfi = 0; nfi < 4; nfi++) {
                const int n = wn * 32 + nfi * 8 + (lane & 3) * 2;
                float bd0 = s_bdt[n], bd1 = s_bdt[n + 1];
                float u00 = acc[mf][nfi][0] * softplus_f(acc[mf][nfi + 4][0] + bd0);
                float u01 = acc[mf][nfi][1] * softplus_f(acc[mf][nfi + 4][1] + bd1);
                float u10 = acc[mf][nfi][2] * softplus_f(acc[mf][nfi + 4][2] + bd0);
                float u11 = acc[mf][nfi][3] * softplus_f(acc[mf][nfi + 4][3] + bd1);
                *reinterpret_cast<float2*>(g_u + tok0 * DI_ + n)       = make_float2(u00, u01);
                *reinterpret_cast<float2*>(g_u + (tok0 + 8) * DI_ + n) = make_float2(u10, u11);
                float p0 = u00 + u10, p1 = u01 + u11;
                #pragma unroll
                for (int m = 4; m <= 16; m <<= 1) {
                    p0 += __shfl_xor_sync(0xffffffffu, p0, m);
                    p1 += __shfl_xor_sync(0xffffffffu, p1, m);
                }
                if ((lane >> 2) == 0) {
                    atomicAdd(&s_sums[n], p0);
                    atomicAdd(&s_sums[n + 1], p1);
                }
            }
        }
        __syncthreads();
        if (tid < 128) {
            g_sums[(size_t)tile * DI_ + tid] = s_sums[tid];
            s_sums[tid] = 0.f;
        }
    }
}

// =====================================================================
// K2: exclusive scan of chunk sums
// =====================================================================
__global__ void k2_scan(void)
{
    const int b = blockIdx.x >> 7;
    const int c = blockIdx.x & 127;
    const int t = threadIdx.x;
    __shared__ float part[64];

    float local[27];
    float s = 0.f;
    #pragma unroll
    for (int i = 0; i < 27; i++) {
        local[i] = g_sums[(b * NCH + t * 27 + i) * DI_ + c];
        s += local[i];
    }
    part[t] = s;
    __syncthreads();
    if (t == 0) {
        float run = 0.f;
        for (int i = 0; i < 64; i++) { float v = part[i]; part[i] = run; run += v; }
    }
    __syncthreads();
    float run = part[t];
    #pragma unroll
    for (int i = 0; i < 27; i++) {
        g_offs[(b * NCH + t * 27 + i) * DI_ + c] = run;
        run += local[i];
    }
}

// =====================================================================
// K3: in-chunk scan -> y ; y@W_out (f32x2) ; +x ; LayerNorm
// =====================================================================
__global__ __launch_bounds__(256, 3)
void k3_kernel(const float* __restrict__ x,
               const float* __restrict__ W_out,
               const float* __restrict__ gamma,
               const float* __restrict__ beta,
               float* __restrict__ out)
{
    extern __shared__ float smem[];
    float* s_yT  = smem + S3_YT;
    ull*   s_w2  = reinterpret_cast<ull*>(smem + S3_W2);
    float* s_off = smem + S3_OFF;
    float* s_mid = smem + S3_MID;

    const int bc    = blockIdx.x;
    const int b     = bc / NCH;
    const int chunk = bc - b * NCH;
    const int l0    = chunk * 64;
    const int tid   = threadIdx.x;

    for (int i = tid; i < 128 * 32; i += 256) {
        int k = i >> 5, j = i & 31;
        s_w2[i] = pack2(W_out[k * 64 + j], W_out[k * 64 + j + 32]);
    }
    if (tid < 128)
        s_off[tid] = g_offs[(b * NCH + chunk) * DI_ + tid];
    __syncthreads();

    {
        const int c = tid & 127, h = tid >> 7;
        const size_t base = ((size_t)b * L_ + l0 + h * 32) * DI_ + c;
        float uv[32];
        #pragma unroll
        for (int i = 0; i < 32; i++) uv[i] = g_u[base + (size_t)i * DI_];
        float ps = 0.f;
        #pragma unroll
        for (int i = 0; i < 32; i++) ps += uv[i];
        if (h == 0) s_mid[c] = ps;
        __syncthreads();
        float run = s_off[c] + (h ? s_mid[c] : 0.f);
        float bufv[4];
        #pragma unroll
        for (int i = 0; i < 32; i++) {
            run += uv[i];
            float r = g_res[base + (size_t)i * DI_];
            bufv[i & 3] = run * r;
            if ((i & 3) == 3)
                *reinterpret_cast<float4*>(s_yT + c * 68 + h * 32 + i - 3) =
                    make_float4(bufv[0], bufv[1], bufv[2], bufv[3]);
        }
    }
    __syncthreads();

    {
        const int w = tid >> 5, lane = tid & 31;
        ull acc[4][2];
        #pragma unroll
        for (int rp = 0; rp < 4; rp++) { acc[rp][0] = 0ull; acc[rp][1] = 0ull; }

        #pragma unroll 4
        for (int k = 0; k < 128; k++) {
            const float* yp = s_yT + k * 68 + 8 * w;
            float4 Y0 = *reinterpret_cast<const float4*>(yp);
            float4 Y1 = *reinterpret_cast<const float4*>(yp + 4);
            float2 wf = unpack2(s_w2[k * 32 + lane]);
            ull w0 = pack2(wf.x, wf.x), w1 = pack2(wf.y, wf.y);
            ull y0 = pack2(Y0.x, Y0.y), y1 = pack2(Y0.z, Y0.w);
            ull y2 = pack2(Y1.x, Y1.y), y3 = pack2(Y1.z, Y1.w);
            acc[0][0] = ffma2(y0, w0, acc[0][0]); acc[0][1] = ffma2(y0, w1, acc[0][1]);
            acc[1][0] = ffma2(y1, w0, acc[1][0]); acc[1][1] = ffma2(y1, w1, acc[1][1]);
            acc[2][0] = ffma2(y2, w0, acc[2][0]); acc[2][1] = ffma2(y2, w1, acc[2][1]);
            acc[3][0] = ffma2(y3, w0, acc[3][0]); acc[3][1] = ffma2(y3, w1, acc[3][1]);
        }

        const float g0 = gamma[lane],  g1 = gamma[lane + 32];
        const float be0 = beta[lane],  be1 = beta[lane + 32];
        #pragma unroll
        for (int rp = 0; rp < 4; rp++) {
            float2 zc0 = unpack2(acc[rp][0]);
            float2 zc1 = unpack2(acc[rp][1]);
            #pragma unroll
            for (int rr = 0; rr < 2; rr++) {
                const int l = l0 + 8 * w + 2 * rp + rr;
                const size_t xb = ((size_t)b * L_ + l) * C_;
                float z0 = (rr ? zc0.y : zc0.x) + x[xb + lane];
                float z1 = (rr ? zc1.y : zc1.x) + x[xb + lane + 32];
                float s  = z0 + z1;
                float s2 = z0 * z0 + z1 * z1;
                #pragma unroll
                for (int off = 16; off; off >>= 1) {
                    s  += __shfl_xor_sync(0xffffffffu, s,  off);
                    s2 += __shfl_xor_sync(0xffffffffu, s2, off);
                }
                float mu  = s * (1.f / 64.f);
                float var = s2 * (1.f / 64.f) - mu * mu;
                float inv = rsqrtf(var + EPS_);
                out[xb + lane]      = fmaf(g0, (z0 - mu) * inv, be0);
                out[xb + lane + 32] = fmaf(g1, (z1 - mu) * inv, be1);
            }
        }
    }
}

// =====================================================================
extern "C" void kernel_launch(void* const* d_in, const int* in_sizes, int n_in,
                              void* d_out, int out_size)
{
    (void)in_sizes; (void)n_in; (void)out_size;
    const float* x      = (const float*)d_in[0];
    const float* W_in   = (const float*)d_in[1];
    const float* conv_w = (const float*)d_in[2];
    const float* conv_b = (const float*)d_in[3];
    const float* W_x    = (const float*)d_in[4];
    const float* W_dt   = (const float*)d_in[5];
    const float* b_dt   = (const float*)d_in[6];
    const float* W_out  = (const float*)d_in[7];
    const float* gamma  = (const float*)d_in[8];
    const float* beta   = (const float*)d_in[9];
    float* out = (float*)d_out;

    const int smem1 = K1_SMEM_FLOATS * 4;
    const int smem3 = K3_SMEM_FLOATS * 4;
    cudaFuncSetAttribute(k1a_kernel, cudaFuncAttributeMaxDynamicSharedMemorySize, smem1);
    cudaFuncSetAttribute(kb_kernel,  cudaFuncAttributeMaxDynamicSharedMemorySize, KB_SMEM);
    cudaFuncSetAttribute(k3_kernel,  cudaFuncAttributeMaxDynamicSharedMemorySize, smem3);

    k_prep<<<16, 256>>>(W_x, W_dt);
    k1a_kernel<<<NTIL, 256, smem1>>>(x, W_in, conv_w, conv_b);
    kb_kernel<<<148, 256, KB_SMEM>>>(b_dt);
    k2_scan<<<B_ * 128, 64>>>();
    k3_kernel<<<NTIL, 256, smem3>>>(x, W_out, gamma, beta, out);
}

// round 5
// speedup vs baseline: 2.5518x; 1.0366x over previous
#include <cuda_runtime.h>
#include <cuda_bf16.h>
#include <cstdint>

typedef unsigned long long ull;
typedef unsigned int u32;
typedef unsigned short u16;

#define B_   2
#define L_   110592
#define C_   64
#define DI_  128
#define NCH  1728               // 64-token chunks per batch
#define NTIL (B_ * NCH)         // 3456
#define EPS_ 1e-3f

// ---- k1a smem layout (bytes) ----
#define P1_W1H 0                // 32KB  W_in hi image [64k][256n]
#define P1_W1L 32768            // 32KB  W_in lo
#define P1_A1H 65536            // 12288 x hi image [96r][64c]
#define P1_A1L 77824            // 12288 x lo
#define P1_XS  90112            // 67*130 fp32 = 34840 -> 35840
#define P1_XCH 125952           // 16KB xc hi image [64t][128c]
#define P1_XCL 142336           // 16KB xc lo
#define P1_SMEM 158720
// ---- K3 smem layout (floats) ----
#define S3_YT   0
#define S3_W2   8704
#define S3_OFF  16896
#define S3_MID  17024
#define K3_SMEM_FLOATS 17152
// ---- kb smem layout (bytes) ----
#define KB_BH   0
#define KB_BL   65536
#define KB_A    131072
#define KB_BDT  196608
#define KB_SUMS 197120
#define KB_SMEM 197632

// ---------------- global scratch ----------------
__device__ float g_u[(size_t)B_ * L_ * DI_];
__device__ float g_res[(size_t)B_ * L_ * DI_];   // silu(res)
__device__ float g_sums[NTIL * DI_];
__device__ float g_offs[NTIL * DI_];
__device__ uint4 g_xch4[(size_t)NTIL * 1024];    // xc hi chunk images (16KB)
__device__ uint4 g_xcl4[(size_t)NTIL * 1024];
__device__ uint4 g_Bh4[4096];                    // W2 hi image [128k][256n]
__device__ uint4 g_Bl4[4096];
__device__ uint4 g_W1h4[2048];                   // W_in hi image [64k][256n]
__device__ uint4 g_W1l4[2048];

// ---------------- helpers ----------------
__device__ __forceinline__ ull ffma2(ull a, ull b, ull c) {
    ull d; asm("fma.rn.f32x2 %0, %1, %2, %3;" : "=l"(d) : "l"(a), "l"(b), "l"(c)); return d;
}
__device__ __forceinline__ ull pack2(float lo, float hi) {
    ull d; asm("mov.b64 %0, {%1, %2};" : "=l"(d) : "f"(lo), "f"(hi)); return d;
}
__device__ __forceinline__ float2 unpack2(ull p) {
    float lo, hi; asm("mov.b64 {%0, %1}, %2;" : "=f"(lo), "=f"(hi) : "l"(p));
    return make_float2(lo, hi);
}
__device__ __forceinline__ float softplus_f(float v) {
    return (v > 15.f) ? v : log1pf(__expf(v));
}
__device__ __forceinline__ u32 smem_u32(const void* p) {
    u32 a; asm("{ .reg .u64 t; cvta.to.shared.u64 t, %1; cvt.u32.u64 %0, t; }"
               : "=r"(a) : "l"(p));
    return a;
}
__device__ __forceinline__ void mma_bf16(float& d0, float& d1, float& d2, float& d3,
                                         u32 a0, u32 a1, u32 a2, u32 a3,
                                         u32 b0, u32 b1) {
    asm volatile("mma.sync.aligned.m16n8k16.row.col.f32.bf16.bf16.f32 "
                 "{%0,%1,%2,%3}, {%4,%5,%6,%7}, {%8,%9}, {%0,%1,%2,%3};"
                 : "+f"(d0), "+f"(d1), "+f"(d2), "+f"(d3)
                 : "r"(a0), "r"(a1), "r"(a2), "r"(a3), "r"(b0), "r"(b1));
}
__device__ __forceinline__ void ldmatrix_x4(u32& r0, u32& r1, u32& r2, u32& r3, u32 addr) {
    asm volatile("ldmatrix.sync.aligned.m8n8.x4.shared.b16 {%0,%1,%2,%3}, [%4];"
                 : "=r"(r0), "=r"(r1), "=r"(r2), "=r"(r3) : "r"(addr));
}
__device__ __forceinline__ void ldmatrix_x2t(u32& r0, u32& r1, u32 addr) {
    asm volatile("ldmatrix.sync.aligned.m8n8.x2.trans.shared.b16 {%0,%1}, [%2];"
                 : "=r"(r0), "=r"(r1) : "r"(addr));
}
#define CP_ASYNC16(dst, src) \
    asm volatile("cp.async.cg.shared.global [%0], [%1], 16;" :: "r"(dst), "l"(src))
#define CP_COMMIT() asm volatile("cp.async.commit_group;")
#define CP_WAIT(n)  asm volatile("cp.async.wait_group %0;" :: "n"(n))

__device__ __forceinline__ void bf16_split(float v, u16& h, u16& l) {
    __nv_bfloat16 hb = __float2bfloat16(v);
    __nv_bfloat16 lb = __float2bfloat16(v - __bfloat162float(hb));
    h = *reinterpret_cast<u16*>(&hb);
    l = *reinterpret_cast<u16*>(&lb);
}

// =====================================================================
// k_prep: W2 = [W_x[:, :128] | W_dt] and W_in -> bf16 hi/lo swizzled
// images: off = k*512 + ((n>>3 ^ (k&7))<<4) + (n&7)*2
// =====================================================================
__global__ void k_prep(const float* __restrict__ W_x,
                       const float* __restrict__ W_dt,
                       const float* __restrict__ W_in)
{
    u16* bh = reinterpret_cast<u16*>(g_Bh4);
    u16* bl = reinterpret_cast<u16*>(g_Bl4);
    u16* wh = reinterpret_cast<u16*>(g_W1h4);
    u16* wl = reinterpret_cast<u16*>(g_W1l4);
    int idx = blockIdx.x * 256 + threadIdx.x;
    for (int i = idx; i < 128 * 256; i += gridDim.x * 256) {
        int k = i >> 8, n = i & 255;
        float w = (n < 128) ? W_x[(size_t)k * 144 + n] : W_dt[(size_t)k * 128 + (n - 128)];
        u16 h, l; bf16_split(w, h, l);
        u32 off = (u32)k * 512 + ((((n >> 3) ^ (k & 7))) << 4) + (n & 7) * 2;
        bh[off >> 1] = h; bl[off >> 1] = l;
    }
    for (int i = idx; i < 64 * 256; i += gridDim.x * 256) {
        int k = i >> 8, n = i & 255;
        float w = W_in[(size_t)k * 256 + n];
        u16 h, l; bf16_split(w, h, l);
        u32 off = (u32)k * 512 + ((((n >> 3) ^ (k & 7))) << 4) + (n & 7) * 2;
        wh[off >> 1] = h; wl[off >> 1] = l;
    }
}

// =====================================================================
// k1a: tensor GEMM1 x@W_in (split-bf16 mma) -> xs smem + silu(res) gmem ;
//      conv4+silu -> xc bf16 hi/lo images -> global
// A image: row r (token l0-1+r, 0..66 valid, 96 padded), ch c (0..63):
//   byte = r*128 + ((c>>3 ^ (r&7))<<4) + (c&7)*2
// =====================================================================
__global__ __launch_bounds__(512, 1)
void k1a_kernel(const float* __restrict__ x,
                const float* __restrict__ conv_w,
                const float* __restrict__ conv_b)
{
    extern __shared__ char sm[];
    const u32 smb = smem_u32(sm);
    float* s_xs = reinterpret_cast<float*>(sm + P1_XS);     // [67][130]

    const int bc    = blockIdx.x;
    const int b     = bc / NCH;
    const int chunk = bc - b * NCH;
    const int l0    = chunk * 64;
    const int tid   = threadIdx.x;

    // stage W_in images (64KB)
    {
        uint4* dh = reinterpret_cast<uint4*>(sm + P1_W1H);
        uint4* dl = reinterpret_cast<uint4*>(sm + P1_W1L);
        for (int i = tid; i < 2048; i += 512) { dh[i] = g_W1h4[i]; dl[i] = g_W1l4[i]; }
    }

    // load x rows l0-1..l0+65, convert to bf16 hi/lo A image
    for (int i = tid; i < 67 * 16; i += 512) {
        int r = i >> 4, q = i & 15;
        int l = l0 - 1 + r;
        float4 v = make_float4(0.f, 0.f, 0.f, 0.f);
        if (l >= 0 && l < L_)
            v = reinterpret_cast<const float4*>(x + ((size_t)b * L_ + l) * C_)[q];
        u16 h0,l0_,h1,l1,h2,l2,h3,l3;
        bf16_split(v.x, h0, l0_); bf16_split(v.y, h1, l1);
        bf16_split(v.z, h2, l2);  bf16_split(v.w, h3, l3);
        ull hv = (ull)h0 | ((ull)h1 << 16) | ((ull)h2 << 32) | ((ull)h3 << 48);
        ull lv = (ull)l0_ | ((ull)l1 << 16) | ((ull)l2 << 32) | ((ull)l3 << 48);
        u32 off = (u32)r * 128 + ((((q >> 1) ^ (r & 7))) << 4) + (q & 1) * 8;
        *reinterpret_cast<ull*>(sm + P1_A1H + off) = hv;
        *reinterpret_cast<ull*>(sm + P1_A1L + off) = lv;
    }
    __syncthreads();

    // GEMM1: [96x64] @ [64x256], 16 warps = 2M x 8N
    {
        const int w = tid >> 5, lane = tid & 31;
        const int wm = w >> 3;          // 0..1 : rows wm*48 + mf*16
        const int wn = w & 7;           // 0..7 : cols wn*32

        float acc[3][4][4];
        #pragma unroll
        for (int mf = 0; mf < 3; mf++)
            #pragma unroll
            for (int nf = 0; nf < 4; nf++)
                #pragma unroll
                for (int j = 0; j < 4; j++) acc[mf][nf][j] = 0.f;

        const u32 aHb = smb + P1_A1H, aLb = smb + P1_A1L;
        const u32 bHb = smb + P1_W1H, bLb = smb + P1_W1L;

        #pragma unroll
        for (int ks = 0; ks < 4; ks++) {
            u32 ah[3][4], al[3][4];
            #pragma unroll
            for (int mf = 0; mf < 3; mf++) {
                int row = wm * 48 + mf * 16 + (lane & 15);
                int ck  = ks * 2 + (lane >> 4);
                u32 off = (u32)row * 128 + (((ck ^ (row & 7))) << 4);
                ldmatrix_x4(ah[mf][0], ah[mf][1], ah[mf][2], ah[mf][3], aHb + off);
                ldmatrix_x4(al[mf][0], al[mf][1], al[mf][2], al[mf][3], aLb + off);
            }
            int krow = ks * 16 + (lane & 15);
            u32 krbase = (u32)krow * 512;
            int kx = krow & 7;
            #pragma unroll
            for (int nf = 0; nf < 4; nf++) {
                int n0 = wn * 32 + nf * 8;
                u32 off = krbase + ((((n0 >> 3) ^ kx)) << 4);
                u32 bh0, bh1, bl0, bl1;
                ldmatrix_x2t(bh0, bh1, bHb + off);
                ldmatrix_x2t(bl0, bl1, bLb + off);
                #pragma unroll
                for (int mf = 0; mf < 3; mf++) {
                    mma_bf16(acc[mf][nf][0], acc[mf][nf][1], acc[mf][nf][2], acc[mf][nf][3],
                             ah[mf][0], ah[mf][1], ah[mf][2], ah[mf][3], bh0, bh1);
                    mma_bf16(acc[mf][nf][0], acc[mf][nf][1], acc[mf][nf][2], acc[mf][nf][3],
                             ah[mf][0], ah[mf][1], ah[mf][2], ah[mf][3], bl0, bl1);
                    mma_bf16(acc[mf][nf][0], acc[mf][nf][1], acc[mf][nf][2], acc[mf][nf][3],
                             al[mf][0], al[mf][1], al[mf][2], al[mf][3], bh0, bh1);
                }
            }
        }

        // epilogue: xs -> smem (wn<4), silu(res) -> gmem (wn>=4)
        #pragma unroll
        for (int mf = 0; mf < 3; mf++) {
            const int r0 = wm * 48 + mf * 16 + (lane >> 2);
            #pragma unroll
            for (int nf = 0; nf < 4; nf++) {
                const int n = wn * 32 + nf * 8 + (lane & 3) * 2;
                if (wn < 4) {
                    if (r0 < 67)
                        *reinterpret_cast<float2*>(s_xs + r0 * 130 + n) =
                            make_float2(acc[mf][nf][0], acc[mf][nf][1]);
                    if (r0 + 8 < 67)
                        *reinterpret_cast<float2*>(s_xs + (r0 + 8) * 130 + n) =
                            make_float2(acc[mf][nf][2], acc[mf][nf][3]);
                } else {
                    const int nn = n - 128;
                    if (r0 >= 1 && r0 <= 64) {
                        float v0 = acc[mf][nf][0], v1 = acc[mf][nf][1];
                        *reinterpret_cast<float2*>(
                            g_res + ((size_t)b * L_ + l0 + r0 - 1) * DI_ + nn) =
                            make_float2(v0 / (1.f + __expf(-v0)), v1 / (1.f + __expf(-v1)));
                    }
                    const int r1 = r0 + 8;
                    if (r1 >= 1 && r1 <= 64) {
                        float v0 = acc[mf][nf][2], v1 = acc[mf][nf][3];
                        *reinterpret_cast<float2*>(
                            g_res + ((size_t)b * L_ + l0 + r1 - 1) * DI_ + nn) =
                            make_float2(v0 / (1.f + __expf(-v0)), v1 / (1.f + __expf(-v1)));
                    }
                }
            }
        }
    }
    __syncthreads();

    // conv k=4 + silu -> bf16 hi/lo xc image
    {
        u16* imgh = reinterpret_cast<u16*>(sm + P1_XCH);
        u16* imgl = reinterpret_cast<u16*>(sm + P1_XCL);
        const int cch = tid & 127, qtr = tid >> 7;   // 0..3
        const float cw0 = conv_w[0 * 128 + cch];
        const float cw1 = conv_w[1 * 128 + cch];
        const float cw2 = conv_w[2 * 128 + cch];
        const float cw3 = conv_w[3 * 128 + cch];
        const float cb  = conv_b[cch];
        const int t0 = qtr * 16;
        float v0 = s_xs[(t0 + 0) * 130 + cch];
        float v1 = s_xs[(t0 + 1) * 130 + cch];
        float v2 = s_xs[(t0 + 2) * 130 + cch];
        #pragma unroll 4
        for (int t = t0; t < t0 + 16; t++) {
            float v3 = s_xs[(t + 3) * 130 + cch];
            float z = fmaf(cw0, v0, fmaf(cw1, v1, fmaf(cw2, v2, fmaf(cw3, v3, cb))));
            float sig = 1.f / (1.f + __expf(-z));
            float v = z * sig;
            u16 h, l; bf16_split(v, h, l);
            u32 off = (u32)t * 256 + ((((cch >> 3) ^ (t & 7))) << 4) + (cch & 7) * 2;
            imgh[off >> 1] = h; imgl[off >> 1] = l;
            v0 = v1; v1 = v2; v2 = v3;
        }
    }
    __syncthreads();

    {
        const uint4* sh = reinterpret_cast<const uint4*>(sm + P1_XCH);
        const uint4* sl = reinterpret_cast<const uint4*>(sm + P1_XCL);
        for (int i = tid; i < 1024; i += 512) {
            g_xch4[(size_t)bc * 1024 + i] = sh[i];
            g_xcl4[(size_t)bc * 1024 + i] = sl[i];
        }
    }
}

// =====================================================================
// kb: persistent tensor GEMM2 (unchanged from R4)
// =====================================================================
__global__ __launch_bounds__(256, 1)
void kb_kernel(const float* __restrict__ b_dt)
{
    extern __shared__ char sm[];
    const u32 smb = smem_u32(sm);
    float* s_bdt  = reinterpret_cast<float*>(sm + KB_BDT);
    float* s_sums = reinterpret_cast<float*>(sm + KB_SUMS);

    const int tid  = threadIdx.x;
    const int w    = tid >> 5;
    const int lane = tid & 31;
    const int wm   = w >> 2;
    const int wn   = w & 3;

    {
        uint4* dh = reinterpret_cast<uint4*>(sm + KB_BH);
        uint4* dl = reinterpret_cast<uint4*>(sm + KB_BL);
        for (int i = tid; i < 4096; i += 256) { dh[i] = g_Bh4[i]; dl[i] = g_Bl4[i]; }
    }
    if (tid < 128) s_bdt[tid] = b_dt[tid];
    if (tid < 128) s_sums[tid] = 0.f;

    int tile0 = blockIdx.x;
    if (tile0 < NTIL) {
        u32 dh = smb + KB_A;
        const char* srcH = reinterpret_cast<const char*>(g_xch4 + (size_t)tile0 * 1024);
        const char* srcL = reinterpret_cast<const char*>(g_xcl4 + (size_t)tile0 * 1024);
        for (int i = tid; i < 1024; i += 256) {
            CP_ASYNC16(dh + i * 16,         srcH + i * 16);
            CP_ASYNC16(dh + 16384 + i * 16, srcL + i * 16);
        }
    }
    CP_COMMIT();

    int it = 0;
    for (int tile = tile0; tile < NTIL; tile += gridDim.x, it++) {
        const int buf = it & 1;
        const int nxt = tile + gridDim.x;
        if (nxt < NTIL) {
            u32 dh = smb + KB_A + (buf ^ 1) * 32768;
            const char* srcH = reinterpret_cast<const char*>(g_xch4 + (size_t)nxt * 1024);
            const char* srcL = reinterpret_cast<const char*>(g_xcl4 + (size_t)nxt * 1024);
            for (int i = tid; i < 1024; i += 256) {
                CP_ASYNC16(dh + i * 16,         srcH + i * 16);
                CP_ASYNC16(dh + 16384 + i * 16, srcL + i * 16);
            }
            CP_COMMIT();
            CP_WAIT(1);
        } else {
            CP_WAIT(0);
        }
        __syncthreads();

        const u32 aH = smb + KB_A + buf * 32768;
        const u32 aL = aH + 16384;
        const u32 bH = smb + KB_BH;
        const u32 bL = smb + KB_BL;

        float acc[2][8][4];
        #pragma unroll
        for (int mf = 0; mf < 2; mf++)
            #pragma unroll
            for (int nf = 0; nf < 8; nf++)
                #pragma unroll
                for (int j = 0; j < 4; j++) acc[mf][nf][j] = 0.f;

        #pragma unroll 1
        for (int ks = 0; ks < 8; ks++) {
            u32 ah[2][4], al[2][4];
            #pragma unroll
            for (int mf = 0; mf < 2; mf++) {
                int row = wm * 32 + mf * 16 + (lane & 15);
                int ck = ks * 2 + (lane >> 4);
                u32 off = (u32)row * 256 + (((ck ^ (row & 7))) << 4);
                ldmatrix_x4(ah[mf][0], ah[mf][1], ah[mf][2], ah[mf][3], aH + off);
                ldmatrix_x4(al[mf][0], al[mf][1], al[mf][2], al[mf][3], aL + off);
            }
            int krow = ks * 16 + (lane & 15);
            u32 krbase = (u32)krow * 512;
            int kx = krow & 7;
            #pragma unroll
            for (int nfi = 0; nfi < 8; nfi++) {
                int n0 = (nfi < 4) ? (wn * 32 + nfi * 8) : (128 + wn * 32 + (nfi - 4) * 8);
                u32 off = krbase + ((((n0 >> 3) ^ kx)) << 4);
                u32 bh0, bh1, bl0, bl1;
                ldmatrix_x2t(bh0, bh1, bH + off);
                ldmatrix_x2t(bl0, bl1, bL + off);
                #pragma unroll
                for (int mf = 0; mf < 2; mf++) {
                    mma_bf16(acc[mf][nfi][0], acc[mf][nfi][1], acc[mf][nfi][2], acc[mf][nfi][3],
                             ah[mf][0], ah[mf][1], ah[mf][2], ah[mf][3], bh0, bh1);
                    mma_bf16(acc[mf][nfi][0], acc[mf][nfi][1], acc[mf][nfi][2], acc[mf][nfi][3],
                             ah[mf][0], ah[mf][1], ah[mf][2], ah[mf][3], bl0, bl1);
                    mma_bf16(acc[mf][nfi][0], acc[mf][nfi][1], acc[mf][nfi][2], acc[mf][nfi][3],
                             al[mf][0], al[mf][1], al[mf][2], al[mf][3], bh0, bh1);
                }
            }
        }

        #pragma unroll
        for (int mf = 0; mf < 2; mf++) {
            const int r0 = wm * 32 + mf * 16 + (lane >> 2);
            const size_t tok0 = (size_t)tile * 64 + r0;
            #pragma unroll
            for (int nfi = 0; nfi < 4; nfi++) {
                const int n = wn * 32 + nfi * 8 + (lane & 3) * 2;
                float bd0 = s_bdt[n], bd1 = s_bdt[n + 1];
                float u00 = acc[mf][nfi][0] * softplus_f(acc[mf][nfi + 4][0] + bd0);
                float u01 = acc[mf][nfi][1] * softplus_f(acc[mf][nfi + 4][1] + bd1);
                float u10 = acc[mf][nfi][2] * softplus_f(acc[mf][nfi + 4][2] + bd0);
                float u11 = acc[mf][nfi][3] * softplus_f(acc[mf][nfi + 4][3] + bd1);
                *reinterpret_cast<float2*>(g_u + tok0 * DI_ + n)       = make_float2(u00, u01);
                *reinterpret_cast<float2*>(g_u + (tok0 + 8) * DI_ + n) = make_float2(u10, u11);
                float p0 = u00 + u10, p1 = u01 + u11;
                #pragma unroll
                for (int m = 4; m <= 16; m <<= 1) {
                    p0 += __shfl_xor_sync(0xffffffffu, p0, m);
                    p1 += __shfl_xor_sync(0xffffffffu, p1, m);
                }
                if ((lane >> 2) == 0) {
                    atomicAdd(&s_sums[n], p0);
                    atomicAdd(&s_sums[n + 1], p1);
                }
            }
        }
        __syncthreads();
        if (tid < 128) {
            g_sums[(size_t)tile * DI_ + tid] = s_sums[tid];
            s_sums[tid] = 0.f;
        }
    }
}

// =====================================================================
// K2: exclusive scan of chunk sums
// =====================================================================
__global__ void k2_scan(void)
{
    const int b = blockIdx.x >> 7;
    const int c = blockIdx.x & 127;
    const int t = threadIdx.x;
    __shared__ float part[64];

    float local[27];
    float s = 0.f;
    #pragma unroll
    for (int i = 0; i < 27; i++) {
        local[i] = g_sums[(b * NCH + t * 27 + i) * DI_ + c];
        s += local[i];
    }
    part[t] = s;
    __syncthreads();
    if (t == 0) {
        float run = 0.f;
        for (int i = 0; i < 64; i++) { float v = part[i]; part[i] = run; run += v; }
    }
    __syncthreads();
    float run = part[t];
    #pragma unroll
    for (int i = 0; i < 27; i++) {
        g_offs[(b * NCH + t * 27 + i) * DI_ + c] = run;
        run += local[i];
    }
}

// =====================================================================
// K3: in-chunk scan -> y ; y@W_out (f32x2) ; +x ; LayerNorm
// =====================================================================
__global__ __launch_bounds__(256, 3)
void k3_kernel(const float* __restrict__ x,
               const float* __restrict__ W_out,
               const float* __restrict__ gamma,
               const float* __restrict__ beta,
               float* __restrict__ out)
{
    extern __shared__ float smem[];
    float* s_yT  = smem + S3_YT;
    ull*   s_w2  = reinterpret_cast<ull*>(smem + S3_W2);
    float* s_off = smem + S3_OFF;
    float* s_mid = smem + S3_MID;

    const int bc    = blockIdx.x;
    const int b     = bc / NCH;
    const int chunk = bc - b * NCH;
    const int l0    = chunk * 64;
    const int tid   = threadIdx.x;

    for (int i = tid; i < 128 * 32; i += 256) {
        int k = i >> 5, j = i & 31;
        s_w2[i] = pack2(W_out[k * 64 + j], W_out[k * 64 + j + 32]);
    }
    if (tid < 128)
        s_off[tid] = g_offs[(b * NCH + chunk) * DI_ + tid];
    __syncthreads();

    {
        const int c = tid & 127, h = tid >> 7;
        const size_t base = ((size_t)b * L_ + l0 + h * 32) * DI_ + c;
        float uv[32];
        #pragma unroll
        for (int i = 0; i < 32; i++) uv[i] = g_u[base + (size_t)i * DI_];
        float ps = 0.f;
        #pragma unroll
        for (int i = 0; i < 32; i++) ps += uv[i];
        if (h == 0) s_mid[c] = ps;
        __syncthreads();
        float run = s_off[c] + (h ? s_mid[c] : 0.f);
        float bufv[4];
        #pragma unroll
        for (int i = 0; i < 32; i++) {
            run += uv[i];
            float r = g_res[base + (size_t)i * DI_];
            bufv[i & 3] = run * r;
            if ((i & 3) == 3)
                *reinterpret_cast<float4*>(s_yT + c * 68 + h * 32 + i - 3) =
                    make_float4(bufv[0], bufv[1], bufv[2], bufv[3]);
        }
    }
    __syncthreads();

    {
        const int w = tid >> 5, lane = tid & 31;
        ull acc[4][2];
        #pragma unroll
        for (int rp = 0; rp < 4; rp++) { acc[rp][0] = 0ull; acc[rp][1] = 0ull; }

        #pragma unroll 4
        for (int k = 0; k < 128; k++) {
            const float* yp = s_yT + k * 68 + 8 * w;
            float4 Y0 = *reinterpret_cast<const float4*>(yp);
            float4 Y1 = *reinterpret_cast<const float4*>(yp + 4);
            float2 wf = unpack2(s_w2[k * 32 + lane]);
            ull w0 = pack2(wf.x, wf.x), w1 = pack2(wf.y, wf.y);
            ull y0 = pack2(Y0.x, Y0.y), y1 = pack2(Y0.z, Y0.w);
            ull y2 = pack2(Y1.x, Y1.y), y3 = pack2(Y1.z, Y1.w);
            acc[0][0] = ffma2(y0, w0, acc[0][0]); acc[0][1] = ffma2(y0, w1, acc[0][1]);
            acc[1][0] = ffma2(y1, w0, acc[1][0]); acc[1][1] = ffma2(y1, w1, acc[1][1]);
            acc[2][0] = ffma2(y2, w0, acc[2][0]); acc[2][1] = ffma2(y2, w1, acc[2][1]);
            acc[3][0] = ffma2(y3, w0, acc[3][0]); acc[3][1] = ffma2(y3, w1, acc[3][1]);
        }

        const float g0 = gamma[lane],  g1 = gamma[lane + 32];
        const float be0 = beta[lane],  be1 = beta[lane + 32];
        #pragma unroll
        for (int rp = 0; rp < 4; rp++) {
            float2 zc0 = unpack2(acc[rp][0]);
            float2 zc1 = unpack2(acc[rp][1]);
            #pragma unroll
            for (int rr = 0; rr < 2; rr++) {
                const int l = l0 + 8 * w + 2 * rp + rr;
                const size_t xb = ((size_t)b * L_ + l) * C_;
                float z0 = (rr ? zc0.y : zc0.x) + x[xb + lane];
                float z1 = (rr ? zc1.y : zc1.x) + x[xb + lane + 32];
                float s  = z0 + z1;
                float s2 = z0 * z0 + z1 * z1;
                #pragma unroll
                for (int off = 16; off; off >>= 1) {
                    s  += __shfl_xor_sync(0xffffffffu, s,  off);
                    s2 += __shfl_xor_sync(0xffffffffu, s2, off);
                }
                float mu  = s * (1.f / 64.f);
                float var = s2 * (1.f / 64.f) - mu * mu;
                float inv = rsqrtf(var + EPS_);
                out[xb + lane]      = fmaf(g0, (z0 - mu) * inv, be0);
                out[xb + lane + 32] = fmaf(g1, (z1 - mu) * inv, be1);
            }
        }
    }
}

// =====================================================================
extern "C" void kernel_launch(void* const* d_in, const int* in_sizes, int n_in,
                              void* d_out, int out_size)
{
    (void)in_sizes; (void)n_in; (void)out_size;
    const float* x      = (const float*)d_in[0];
    const float* W_in   = (const float*)d_in[1];
    const float* conv_w = (const float*)d_in[2];
    const float* conv_b = (const float*)d_in[3];
    const float* W_x    = (const float*)d_in[4];
    const float* W_dt   = (const float*)d_in[5];
    const float* b_dt   = (const float*)d_in[6];
    const float* W_out  = (const float*)d_in[7];
    const float* gamma  = (const float*)d_in[8];
    const float* beta   = (const float*)d_in[9];
    float* out = (float*)d_out;

    const int smem3 = K3_SMEM_FLOATS * 4;
    cudaFuncSetAttribute(k1a_kernel, cudaFuncAttributeMaxDynamicSharedMemorySize, P1_SMEM);
    cudaFuncSetAttribute(kb_kernel,  cudaFuncAttributeMaxDynamicSharedMemorySize, KB_SMEM);
    cudaFuncSetAttribute(k3_kernel,  cudaFuncAttributeMaxDynamicSharedMemorySize, smem3);

    k_prep<<<16, 256>>>(W_x, W_dt, W_in);
    k1a_kernel<<<NTIL, 512, P1_SMEM>>>(x, conv_w, conv_b);
    kb_kernel<<<148, 256, KB_SMEM>>>(b_dt);
    k2_scan<<<B_ * 128, 64>>>();
    k3_kernel<<<NTIL, 256, smem3>>>(x, W_out, gamma, beta, out);
}

// round 6
// speedup vs baseline: 2.8206x; 1.1053x over previous
#include <cuda_runtime.h>
#include <cuda_bf16.h>
#include <cstdint>

typedef unsigned long long ull;
typedef unsigned int u32;
typedef unsigned short u16;

#define B_   2
#define L_   110592
#define C_   64
#define DI_  128
#define NCH  1728
#define NTIL (B_ * NCH)         // 3456
#define EPS_ 1e-3f

// ---- k1a smem layout (bytes) ----
#define P1_W1H 0                // 32KB
#define P1_W1L 32768            // 32KB
#define P1_XB  65536            // 2 x 17408 x-tile fp32 buffers
#define P1_A1H 100352           // 12288
#define P1_A1L 112640           // 12288
#define P1_XS  124928           // 67*130 fp32 -> 35840
#define P1_XCH 160768           // 16KB
#define P1_XCL 177152           // 16KB
#define P1_SMEM 193536
// ---- K3 smem layout (floats) ----
#define S3_YT   0
#define S3_W2   8704
#define S3_OFF  16896
#define S3_MID  17024
#define K3_SMEM_FLOATS 17152
// ---- kb smem layout (bytes) ----
#define KB_BH   0
#define KB_BL   65536
#define KB_A    131072
#define KB_BDT  196608
#define KB_SUMS 197120
#define KB_SMEM 197632

// ---------------- global scratch ----------------
__device__ float g_u[(size_t)B_ * L_ * DI_];
__device__ float g_res[(size_t)B_ * L_ * DI_];
__device__ float g_sums[NTIL * DI_];
__device__ float g_offs[NTIL * DI_];
__device__ uint4 g_xch4[(size_t)NTIL * 1024];
__device__ uint4 g_xcl4[(size_t)NTIL * 1024];
__device__ uint4 g_Bh4[4096];
__device__ uint4 g_Bl4[4096];
__device__ uint4 g_W1h4[2048];
__device__ uint4 g_W1l4[2048];

// ---------------- helpers ----------------
__device__ __forceinline__ ull ffma2(ull a, ull b, ull c) {
    ull d; asm("fma.rn.f32x2 %0, %1, %2, %3;" : "=l"(d) : "l"(a), "l"(b), "l"(c)); return d;
}
__device__ __forceinline__ ull pack2(float lo, float hi) {
    ull d; asm("mov.b64 %0, {%1, %2};" : "=l"(d) : "f"(lo), "f"(hi)); return d;
}
__device__ __forceinline__ float2 unpack2(ull p) {
    float lo, hi; asm("mov.b64 {%0, %1}, %2;" : "=f"(lo), "=f"(hi) : "l"(p));
    return make_float2(lo, hi);
}
__device__ __forceinline__ float softplus_f(float v) {
    return (v > 10.f) ? v : __logf(1.f + __expf(v));
}
__device__ __forceinline__ u32 smem_u32(const void* p) {
    u32 a; asm("{ .reg .u64 t; cvta.to.shared.u64 t, %1; cvt.u32.u64 %0, t; }"
               : "=r"(a) : "l"(p));
    return a;
}
__device__ __forceinline__ void mma_bf16(float& d0, float& d1, float& d2, float& d3,
                                         u32 a0, u32 a1, u32 a2, u32 a3,
                                         u32 b0, u32 b1) {
    asm volatile("mma.sync.aligned.m16n8k16.row.col.f32.bf16.bf16.f32 "
                 "{%0,%1,%2,%3}, {%4,%5,%6,%7}, {%8,%9}, {%0,%1,%2,%3};"
                 : "+f"(d0), "+f"(d1), "+f"(d2), "+f"(d3)
                 : "r"(a0), "r"(a1), "r"(a2), "r"(a3), "r"(b0), "r"(b1));
}
__device__ __forceinline__ void ldmatrix_x4(u32& r0, u32& r1, u32& r2, u32& r3, u32 addr) {
    asm volatile("ldmatrix.sync.aligned.m8n8.x4.shared.b16 {%0,%1,%2,%3}, [%4];"
                 : "=r"(r0), "=r"(r1), "=r"(r2), "=r"(r3) : "r"(addr));
}
__device__ __forceinline__ void ldmatrix_x2t(u32& r0, u32& r1, u32 addr) {
    asm volatile("ldmatrix.sync.aligned.m8n8.x2.trans.shared.b16 {%0,%1}, [%2];"
                 : "=r"(r0), "=r"(r1) : "r"(addr));
}
#define CP_ASYNC16(dst, src) \
    asm volatile("cp.async.cg.shared.global [%0], [%1], 16;" :: "r"(dst), "l"(src))
#define CP_COMMIT() asm volatile("cp.async.commit_group;")
#define CP_WAIT(n)  asm volatile("cp.async.wait_group %0;" :: "n"(n))

__device__ __forceinline__ void bf16_split(float v, u16& h, u16& l) {
    __nv_bfloat16 hb = __float2bfloat16(v);
    __nv_bfloat16 lb = __float2bfloat16(v - __bfloat162float(hb));
    h = *reinterpret_cast<u16*>(&hb);
    l = *reinterpret_cast<u16*>(&lb);
}

// =====================================================================
// k_prep: W2 and W_in -> bf16 hi/lo swizzled images
// =====================================================================
__global__ void k_prep(const float* __restrict__ W_x,
                       const float* __restrict__ W_dt,
                       const float* __restrict__ W_in)
{
    u16* bh = reinterpret_cast<u16*>(g_Bh4);
    u16* bl = reinterpret_cast<u16*>(g_Bl4);
    u16* wh = reinterpret_cast<u16*>(g_W1h4);
    u16* wl = reinterpret_cast<u16*>(g_W1l4);
    int idx = blockIdx.x * 256 + threadIdx.x;
    for (int i = idx; i < 128 * 256; i += gridDim.x * 256) {
        int k = i >> 8, n = i & 255;
        float w = (n < 128) ? W_x[(size_t)k * 144 + n] : W_dt[(size_t)k * 128 + (n - 128)];
        u16 h, l; bf16_split(w, h, l);
        u32 off = (u32)k * 512 + ((((n >> 3) ^ (k & 7))) << 4) + (n & 7) * 2;
        bh[off >> 1] = h; bl[off >> 1] = l;
    }
    for (int i = idx; i < 64 * 256; i += gridDim.x * 256) {
        int k = i >> 8, n = i & 255;
        float w = W_in[(size_t)k * 256 + n];
        u16 h, l; bf16_split(w, h, l);
        u32 off = (u32)k * 512 + ((((n >> 3) ^ (k & 7))) << 4) + (n & 7) * 2;
        wh[off >> 1] = h; wl[off >> 1] = l;
    }
}

// =====================================================================
// k1a: PERSISTENT: W_in staged once; per tile: cp.async x (dbl-buffered)
//      -> A image -> GEMM1 (split-bf16 mma) -> xs smem + silu(res) gmem
//      -> conv4+silu -> xc images -> global
// =====================================================================
__global__ __launch_bounds__(512, 1)
void k1a_kernel(const float* __restrict__ x,
                const float* __restrict__ conv_w,
                const float* __restrict__ conv_b)
{
    extern __shared__ char sm[];
    const u32 smb = smem_u32(sm);
    float* s_xs = reinterpret_cast<float*>(sm + P1_XS);     // [67][130]

    const int tid = threadIdx.x;

    // stage W_in images (once)
    {
        uint4* dh = reinterpret_cast<uint4*>(sm + P1_W1H);
        uint4* dl = reinterpret_cast<uint4*>(sm + P1_W1L);
        for (int i = tid; i < 2048; i += 512) { dh[i] = g_W1h4[i]; dl[i] = g_W1l4[i]; }
    }
    const float cw0 = conv_w[0 * 128 + (tid & 127)];
    const float cw1 = conv_w[1 * 128 + (tid & 127)];
    const float cw2 = conv_w[2 * 128 + (tid & 127)];
    const float cw3 = conv_w[3 * 128 + (tid & 127)];
    const float cb  = conv_b[tid & 127];

    // prefetch helper: clamped cp.async of x rows l0-1 .. l0+65
    auto prefetch = [&](int tile, int buf) {
        const int b = tile / NCH;
        const int l0 = (tile - b * NCH) * 64;
        const long base = (long)b * L_ + l0 - 1;
        const u32 dst0 = smb + P1_XB + (u32)buf * 17408;
        for (int i = tid; i < 67 * 16; i += 512) {
            int r = i >> 4, q = i & 15;
            long gl = base + r;
            if (gl < 0) gl = 0;
            if (gl > (long)B_ * L_ - 1) gl = (long)B_ * L_ - 1;
            CP_ASYNC16(dst0 + (u32)(r * 64 + q * 4) * 4,
                       x + gl * C_ + q * 4);
        }
    };

    const int tile0 = blockIdx.x;
    if (tile0 < NTIL) prefetch(tile0, 0);
    CP_COMMIT();

    int it = 0;
    for (int tile = tile0; tile < NTIL; tile += gridDim.x, it++) {
        const int buf = it & 1;
        const int b     = tile / NCH;
        const int chunk = tile - b * NCH;
        const int l0    = chunk * 64;

        const int nxt = tile + gridDim.x;
        if (nxt < NTIL) { prefetch(nxt, buf ^ 1); CP_COMMIT(); CP_WAIT(1); }
        else            { CP_WAIT(0); }
        __syncthreads();

        // convert x buffer -> bf16 hi/lo A image (zero OOB rows)
        {
            const float* xb = reinterpret_cast<const float*>(sm + P1_XB + buf * 17408);
            for (int i = tid; i < 67 * 16; i += 512) {
                int r = i >> 4, q = i & 15;
                int l = l0 - 1 + r;
                float4 v = *reinterpret_cast<const float4*>(xb + r * 64 + q * 4);
                if (l < 0 || l >= L_) v = make_float4(0.f, 0.f, 0.f, 0.f);
                u16 h0,lo0,h1,lo1,h2,lo2,h3,lo3;
                bf16_split(v.x, h0, lo0); bf16_split(v.y, h1, lo1);
                bf16_split(v.z, h2, lo2); bf16_split(v.w, h3, lo3);
                ull hv = (ull)h0 | ((ull)h1 << 16) | ((ull)h2 << 32) | ((ull)h3 << 48);
                ull lv = (ull)lo0 | ((ull)lo1 << 16) | ((ull)lo2 << 32) | ((ull)lo3 << 48);
                u32 off = (u32)r * 128 + ((((q >> 1) ^ (r & 7))) << 4) + (q & 1) * 8;
                *reinterpret_cast<ull*>(sm + P1_A1H + off) = hv;
                *reinterpret_cast<ull*>(sm + P1_A1L + off) = lv;
            }
        }
        __syncthreads();

        // GEMM1: [96x64] @ [64x256], 16 warps = 2M x 8N
        {
            const int w = tid >> 5, lane = tid & 31;
            const int wm = w >> 3;
            const int wn = w & 7;

            float acc[3][4][4];
            #pragma unroll
            for (int mf = 0; mf < 3; mf++)
                #pragma unroll
                for (int nf = 0; nf < 4; nf++)
                    #pragma unroll
                    for (int j = 0; j < 4; j++) acc[mf][nf][j] = 0.f;

            const u32 aHb = smb + P1_A1H, aLb = smb + P1_A1L;
            const u32 bHb = smb + P1_W1H, bLb = smb + P1_W1L;

            #pragma unroll
            for (int ks = 0; ks < 4; ks++) {
                u32 ah[3][4], al[3][4];
                #pragma unroll
                for (int mf = 0; mf < 3; mf++) {
                    int row = wm * 48 + mf * 16 + (lane & 15);
                    int ck  = ks * 2 + (lane >> 4);
                    u32 off = (u32)row * 128 + (((ck ^ (row & 7))) << 4);
                    ldmatrix_x4(ah[mf][0], ah[mf][1], ah[mf][2], ah[mf][3], aHb + off);
                    ldmatrix_x4(al[mf][0], al[mf][1], al[mf][2], al[mf][3], aLb + off);
                }
                int krow = ks * 16 + (lane & 15);
                u32 krbase = (u32)krow * 512;
                int kx = krow & 7;
                #pragma unroll
                for (int nf = 0; nf < 4; nf++) {
                    int n0 = wn * 32 + nf * 8;
                    u32 off = krbase + ((((n0 >> 3) ^ kx)) << 4);
                    u32 bh0, bh1, bl0, bl1;
                    ldmatrix_x2t(bh0, bh1, bHb + off);
                    ldmatrix_x2t(bl0, bl1, bLb + off);
                    #pragma unroll
                    for (int mf = 0; mf < 3; mf++) {
                        mma_bf16(acc[mf][nf][0], acc[mf][nf][1], acc[mf][nf][2], acc[mf][nf][3],
                                 ah[mf][0], ah[mf][1], ah[mf][2], ah[mf][3], bh0, bh1);
                        mma_bf16(acc[mf][nf][0], acc[mf][nf][1], acc[mf][nf][2], acc[mf][nf][3],
                                 ah[mf][0], ah[mf][1], ah[mf][2], ah[mf][3], bl0, bl1);
                        mma_bf16(acc[mf][nf][0], acc[mf][nf][1], acc[mf][nf][2], acc[mf][nf][3],
                                 al[mf][0], al[mf][1], al[mf][2], al[mf][3], bh0, bh1);
                    }
                }
            }

            #pragma unroll
            for (int mf = 0; mf < 3; mf++) {
                const int r0 = wm * 48 + mf * 16 + (lane >> 2);
                #pragma unroll
                for (int nf = 0; nf < 4; nf++) {
                    const int n = wn * 32 + nf * 8 + (lane & 3) * 2;
                    if (wn < 4) {
                        if (r0 < 67)
                            *reinterpret_cast<float2*>(s_xs + r0 * 130 + n) =
                                make_float2(acc[mf][nf][0], acc[mf][nf][1]);
                        if (r0 + 8 < 67)
                            *reinterpret_cast<float2*>(s_xs + (r0 + 8) * 130 + n) =
                                make_float2(acc[mf][nf][2], acc[mf][nf][3]);
                    } else {
                        const int nn = n - 128;
                        if (r0 >= 1 && r0 <= 64) {
                            float v0 = acc[mf][nf][0], v1 = acc[mf][nf][1];
                            *reinterpret_cast<float2*>(
                                g_res + ((size_t)b * L_ + l0 + r0 - 1) * DI_ + nn) =
                                make_float2(v0 / (1.f + __expf(-v0)), v1 / (1.f + __expf(-v1)));
                        }
                        const int r1 = r0 + 8;
                        if (r1 >= 1 && r1 <= 64) {
                            float v0 = acc[mf][nf][2], v1 = acc[mf][nf][3];
                            *reinterpret_cast<float2*>(
                                g_res + ((size_t)b * L_ + l0 + r1 - 1) * DI_ + nn) =
                                make_float2(v0 / (1.f + __expf(-v0)), v1 / (1.f + __expf(-v1)));
                        }
                    }
                }
            }
        }
        __syncthreads();

        // conv k=4 + silu -> bf16 hi/lo xc image
        {
            u16* imgh = reinterpret_cast<u16*>(sm + P1_XCH);
            u16* imgl = reinterpret_cast<u16*>(sm + P1_XCL);
            const int cch = tid & 127, qtr = tid >> 7;
            const int t0 = qtr * 16;
            float v0 = s_xs[(t0 + 0) * 130 + cch];
            float v1 = s_xs[(t0 + 1) * 130 + cch];
            float v2 = s_xs[(t0 + 2) * 130 + cch];
            #pragma unroll 4
            for (int t = t0; t < t0 + 16; t++) {
                float v3 = s_xs[(t + 3) * 130 + cch];
                float z = fmaf(cw0, v0, fmaf(cw1, v1, fmaf(cw2, v2, fmaf(cw3, v3, cb))));
                float sig = 1.f / (1.f + __expf(-z));
                float v = z * sig;
                u16 h, l; bf16_split(v, h, l);
                u32 off = (u32)t * 256 + ((((cch >> 3) ^ (t & 7))) << 4) + (cch & 7) * 2;
                imgh[off >> 1] = h; imgl[off >> 1] = l;
                v0 = v1; v1 = v2; v2 = v3;
            }
        }
        __syncthreads();

        {
            const uint4* sh = reinterpret_cast<const uint4*>(sm + P1_XCH);
            const uint4* sl = reinterpret_cast<const uint4*>(sm + P1_XCL);
            for (int i = tid; i < 1024; i += 512) {
                g_xch4[(size_t)tile * 1024 + i] = sh[i];
                g_xcl4[(size_t)tile * 1024 + i] = sl[i];
            }
        }
        __syncthreads();
    }
}

// =====================================================================
// kb: persistent tensor GEMM2 (fast softplus)
// =====================================================================
__global__ __launch_bounds__(256, 1)
void kb_kernel(const float* __restrict__ b_dt)
{
    extern __shared__ char sm[];
    const u32 smb = smem_u32(sm);
    float* s_bdt  = reinterpret_cast<float*>(sm + KB_BDT);
    float* s_sums = reinterpret_cast<float*>(sm + KB_SUMS);

    const int tid  = threadIdx.x;
    const int w    = tid >> 5;
    const int lane = tid & 31;
    const int wm   = w >> 2;
    const int wn   = w & 3;

    {
        uint4* dh = reinterpret_cast<uint4*>(sm + KB_BH);
        uint4* dl = reinterpret_cast<uint4*>(sm + KB_BL);
        for (int i = tid; i < 4096; i += 256) { dh[i] = g_Bh4[i]; dl[i] = g_Bl4[i]; }
    }
    if (tid < 128) s_bdt[tid] = b_dt[tid];
    if (tid < 128) s_sums[tid] = 0.f;

    int tile0 = blockIdx.x;
    if (tile0 < NTIL) {
        u32 dh = smb + KB_A;
        const char* srcH = reinterpret_cast<const char*>(g_xch4 + (size_t)tile0 * 1024);
        const char* srcL = reinterpret_cast<const char*>(g_xcl4 + (size_t)tile0 * 1024);
        for (int i = tid; i < 1024; i += 256) {
            CP_ASYNC16(dh + i * 16,         srcH + i * 16);
            CP_ASYNC16(dh + 16384 + i * 16, srcL + i * 16);
        }
    }
    CP_COMMIT();

    int it = 0;
    for (int tile = tile0; tile < NTIL; tile += gridDim.x, it++) {
        const int buf = it & 1;
        const int nxt = tile + gridDim.x;
        if (nxt < NTIL) {
            u32 dh = smb + KB_A + (buf ^ 1) * 32768;
            const char* srcH = reinterpret_cast<const char*>(g_xch4 + (size_t)nxt * 1024);
            const char* srcL = reinterpret_cast<const char*>(g_xcl4 + (size_t)nxt * 1024);
            for (int i = tid; i < 1024; i += 256) {
                CP_ASYNC16(dh + i * 16,         srcH + i * 16);
                CP_ASYNC16(dh + 16384 + i * 16, srcL + i * 16);
            }
            CP_COMMIT();
            CP_WAIT(1);
        } else {
            CP_WAIT(0);
        }
        __syncthreads();

        const u32 aH = smb + KB_A + buf * 32768;
        const u32 aL = aH + 16384;
        const u32 bH = smb + KB_BH;
        const u32 bL = smb + KB_BL;

        float acc[2][8][4];
        #pragma unroll
        for (int mf = 0; mf < 2; mf++)
            #pragma unroll
            for (int nf = 0; nf < 8; nf++)
                #pragma unroll
                for (int j = 0; j < 4; j++) acc[mf][nf][j] = 0.f;

        #pragma unroll 1
        for (int ks = 0; ks < 8; ks++) {
            u32 ah[2][4], al[2][4];
            #pragma unroll
            for (int mf = 0; mf < 2; mf++) {
                int row = wm * 32 + mf * 16 + (lane & 15);
                int ck = ks * 2 + (lane >> 4);
                u32 off = (u32)row * 256 + (((ck ^ (row & 7))) << 4);
                ldmatrix_x4(ah[mf][0], ah[mf][1], ah[mf][2], ah[mf][3], aH + off);
                ldmatrix_x4(al[mf][0], al[mf][1], al[mf][2], al[mf][3], aL + off);
            }
            int krow = ks * 16 + (lane & 15);
            u32 krbase = (u32)krow * 512;
            int kx = krow & 7;
            #pragma unroll
            for (int nfi = 0; nfi < 8; nfi++) {
                int n0 = (nfi < 4) ? (wn * 32 + nfi * 8) : (128 + wn * 32 + (nfi - 4) * 8);
                u32 off = krbase + ((((n0 >> 3) ^ kx)) << 4);
                u32 bh0, bh1, bl0, bl1;
                ldmatrix_x2t(bh0, bh1, bH + off);
                ldmatrix_x2t(bl0, bl1, bL + off);
                #pragma unroll
                for (int mf = 0; mf < 2; mf++) {
                    mma_bf16(acc[mf][nfi][0], acc[mf][nfi][1], acc[mf][nfi][2], acc[mf][nfi][3],
                             ah[mf][0], ah[mf][1], ah[mf][2], ah[mf][3], bh0, bh1);
                    mma_bf16(acc[mf][nfi][0], acc[mf][nfi][1], acc[mf][nfi][2], acc[mf][nfi][3],
                             ah[mf][0], ah[mf][1], ah[mf][2], ah[mf][3], bl0, bl1);
                    mma_bf16(acc[mf][nfi][0], acc[mf][nfi][1], acc[mf][nfi][2], acc[mf][nfi][3],
                             al[mf][0], al[mf][1], al[mf][2], al[mf][3], bh0, bh1);
                }
            }
        }

        #pragma unroll
        for (int mf = 0; mf < 2; mf++) {
            const int r0 = wm * 32 + mf * 16 + (lane >> 2);
            const size_t tok0 = (size_t)tile * 64 + r0;
            #pragma unroll
            for (int nfi = 0; nfi < 4; nfi++) {
                const int n = wn * 32 + nfi * 8 + (lane & 3) * 2;
                float bd0 = s_bdt[n], bd1 = s_bdt[n + 1];
                float u00 = acc[mf][nfi][0] * softplus_f(acc[mf][nfi + 4][0] + bd0);
                float u01 = acc[mf][nfi][1] * softplus_f(acc[mf][nfi + 4][1] + bd1);
                float u10 = acc[mf][nfi][2] * softplus_f(acc[mf][nfi + 4][2] + bd0);
                float u11 = acc[mf][nfi][3] * softplus_f(acc[mf][nfi + 4][3] + bd1);
                *reinterpret_cast<float2*>(g_u + tok0 * DI_ + n)       = make_float2(u00, u01);
                *reinterpret_cast<float2*>(g_u + (tok0 + 8) * DI_ + n) = make_float2(u10, u11);
                float p0 = u00 + u10, p1 = u01 + u11;
                #pragma unroll
                for (int m = 4; m <= 16; m <<= 1) {
                    p0 += __shfl_xor_sync(0xffffffffu, p0, m);
                    p1 += __shfl_xor_sync(0xffffffffu, p1, m);
                }
                if ((lane >> 2) == 0) {
                    atomicAdd(&s_sums[n], p0);
                    atomicAdd(&s_sums[n + 1], p1);
                }
            }
        }
        __syncthreads();
        if (tid < 128) {
            g_sums[(size_t)tile * DI_ + tid] = s_sums[tid];
            s_sums[tid] = 0.f;
        }
    }
}

// =====================================================================
// K2: exclusive scan of chunk sums
// =====================================================================
__global__ void k2_scan(void)
{
    const int b = blockIdx.x >> 7;
    const int c = blockIdx.x & 127;
    const int t = threadIdx.x;
    __shared__ float part[64];

    float local[27];
    float s = 0.f;
    #pragma unroll
    for (int i = 0; i < 27; i++) {
        local[i] = g_sums[(b * NCH + t * 27 + i) * DI_ + c];
        s += local[i];
    }
    part[t] = s;
    __syncthreads();
    if (t == 0) {
        float run = 0.f;
        for (int i = 0; i < 64; i++) { float v = part[i]; part[i] = run; run += v; }
    }
    __syncthreads();
    float run = part[t];
    #pragma unroll
    for (int i = 0; i < 27; i++) {
        g_offs[(b * NCH + t * 27 + i) * DI_ + c] = run;
        run += local[i];
    }
}

// =====================================================================
// K3: in-chunk scan -> y ; y@W_out (f32x2) ; +x ; LayerNorm
// =====================================================================
__global__ __launch_bounds__(256, 3)
void k3_kernel(const float* __restrict__ x,
               const float* __restrict__ W_out,
               const float* __restrict__ gamma,
               const float* __restrict__ beta,
               float* __restrict__ out)
{
    extern __shared__ float smem[];
    float* s_yT  = smem + S3_YT;
    ull*   s_w2  = reinterpret_cast<ull*>(smem + S3_W2);
    float* s_off = smem + S3_OFF;
    float* s_mid = smem + S3_MID;

    const int bc    = blockIdx.x;
    const int b     = bc / NCH;
    const int chunk = bc - b * NCH;
    const int l0    = chunk * 64;
    const int tid   = threadIdx.x;

    for (int i = tid; i < 128 * 32; i += 256) {
        int k = i >> 5, j = i & 31;
        s_w2[i] = pack2(W_out[k * 64 + j], W_out[k * 64 + j + 32]);
    }
    if (tid < 128)
        s_off[tid] = g_offs[(b * NCH + chunk) * DI_ + tid];
    __syncthreads();

    {
        const int c = tid & 127, h = tid >> 7;
        const size_t base = ((size_t)b * L_ + l0 + h * 32) * DI_ + c;
        float uv[32];
        #pragma unroll
        for (int i = 0; i < 32; i++) uv[i] = g_u[base + (size_t)i * DI_];
        float ps = 0.f;
        #pragma unroll
        for (int i = 0; i < 32; i++) ps += uv[i];
        if (h == 0) s_mid[c] = ps;
        __syncthreads();
        float run = s_off[c] + (h ? s_mid[c] : 0.f);
        float bufv[4];
        #pragma unroll
        for (int i = 0; i < 32; i++) {
            run += uv[i];
            float r = g_res[base + (size_t)i * DI_];
            bufv[i & 3] = run * r;
            if ((i & 3) == 3)
                *reinterpret_cast<float4*>(s_yT + c * 68 + h * 32 + i - 3) =
                    make_float4(bufv[0], bufv[1], bufv[2], bufv[3]);
        }
    }
    __syncthreads();

    {
        const int w = tid >> 5, lane = tid & 31;
        ull acc[4][2];
        #pragma unroll
        for (int rp = 0; rp < 4; rp++) { acc[rp][0] = 0ull; acc[rp][1] = 0ull; }

        #pragma unroll 4
        for (int k = 0; k < 128; k++) {
            const float* yp = s_yT + k * 68 + 8 * w;
            float4 Y0 = *reinterpret_cast<const float4*>(yp);
            float4 Y1 = *reinterpret_cast<const float4*>(yp + 4);
            float2 wf = unpack2(s_w2[k * 32 + lane]);
            ull w0 = pack2(wf.x, wf.x), w1 = pack2(wf.y, wf.y);
            ull y0 = pack2(Y0.x, Y0.y), y1 = pack2(Y0.z, Y0.w);
            ull y2 = pack2(Y1.x, Y1.y), y3 = pack2(Y1.z, Y1.w);
            acc[0][0] = ffma2(y0, w0, acc[0][0]); acc[0][1] = ffma2(y0, w1, acc[0][1]);
            acc[1][0] = ffma2(y1, w0, acc[1][0]); acc[1][1] = ffma2(y1, w1, acc[1][1]);
            acc[2][0] = ffma2(y2, w0, acc[2][0]); acc[2][1] = ffma2(y2, w1, acc[2][1]);
            acc[3][0] = ffma2(y3, w0, acc[3][0]); acc[3][1] = ffma2(y3, w1, acc[3][1]);
        }

        const float g0 = gamma[lane],  g1 = gamma[lane + 32];
        const float be0 = beta[lane],  be1 = beta[lane + 32];
        #pragma unroll
        for (int rp = 0; rp < 4; rp++) {
            float2 zc0 = unpack2(acc[rp][0]);
            float2 zc1 = unpack2(acc[rp][1]);
            #pragma unroll
            for (int rr = 0; rr < 2; rr++) {
                const int l = l0 + 8 * w + 2 * rp + rr;
                const size_t xb = ((size_t)b * L_ + l) * C_;
                float z0 = (rr ? zc0.y : zc0.x) + x[xb + lane];
                float z1 = (rr ? zc1.y : zc1.x) + x[xb + lane + 32];
                float s  = z0 + z1;
                float s2 = z0 * z0 + z1 * z1;
                #pragma unroll
                for (int off = 16; off; off >>= 1) {
                    s  += __shfl_xor_sync(0xffffffffu, s,  off);
                    s2 += __shfl_xor_sync(0xffffffffu, s2, off);
                }
                float mu  = s * (1.f / 64.f);
                float var = s2 * (1.f / 64.f) - mu * mu;
                float inv = rsqrtf(var + EPS_);
                out[xb + lane]      = fmaf(g0, (z0 - mu) * inv, be0);
                out[xb + lane + 32] = fmaf(g1, (z1 - mu) * inv, be1);
            }
        }
    }
}

// =====================================================================
extern "C" void kernel_launch(void* const* d_in, const int* in_sizes, int n_in,
                              void* d_out, int out_size)
{
    (void)in_sizes; (void)n_in; (void)out_size;
    const float* x      = (const float*)d_in[0];
    const float* W_in   = (const float*)d_in[1];
    const float* conv_w = (const float*)d_in[2];
    const float* conv_b = (const float*)d_in[3];
    const float* W_x    = (const float*)d_in[4];
    const float* W_dt   = (const float*)d_in[5];
    const float* b_dt   = (const float*)d_in[6];
    const float* W_out  = (const float*)d_in[7];
    const float* gamma  = (const float*)d_in[8];
    const float* beta   = (const float*)d_in[9];
    float* out = (float*)d_out;

    const int smem3 = K3_SMEM_FLOATS * 4;
    cudaFuncSetAttribute(k1a_kernel, cudaFuncAttributeMaxDynamicSharedMemorySize, P1_SMEM);
    cudaFuncSetAttribute(kb_kernel,  cudaFuncAttributeMaxDynamicSharedMemorySize, KB_SMEM);
    cudaFuncSetAttribute(k3_kernel,  cudaFuncAttributeMaxDynamicSharedMemorySize, smem3);

    k_prep<<<16, 256>>>(W_x, W_dt, W_in);
    k1a_kernel<<<148, 512, P1_SMEM>>>(x, conv_w, conv_b);
    kb_kernel<<<148, 256, KB_SMEM>>>(b_dt);
    k2_scan<<<B_ * 128, 64>>>();
    k3_kernel<<<NTIL, 256, smem3>>>(x, W_out, gamma, beta, out);
}

// round 7
// speedup vs baseline: 3.2511x; 1.1527x over previous
#include <cuda_runtime.h>
#include <cuda_bf16.h>
#include <cstdint>

typedef unsigned long long ull;
typedef unsigned int u32;
typedef unsigned short u16;

#define B_   2
#define L_   110592
#define C_   64
#define DI_  128
#define NCH  1728
#define NTIL (B_ * NCH)         // 3456
#define EPS_ 1e-3f

// ---- k1a smem layout (bytes) ----
#define P1_W1H 0
#define P1_W1L 32768
#define P1_XB  65536
#define P1_A1H 100352
#define P1_A1L 112640
#define P1_XS  124928
#define P1_XCH 160768
#define P1_XCL 177152
#define P1_SMEM 193536
// ---- kb smem layout (bytes) ----
#define KB_BH   0
#define KB_BL   65536
#define KB_A    131072          // 2 x 32KB
#define KB_BDT  196608
#define KB_SUMS 197120
#define KB_SMEM 197632
// ---- k3 smem layout (bytes) ----
#define S3_W3H 0                // 16KB W_out hi image [128k][64n]
#define S3_W3L 16384
#define S3_YH  32768            // 16KB y hi image [64t][128k]
#define S3_YL  49152
#define S3_OFF 65536            // 128 floats
#define S3_MID 66048            // 128 floats
#define S3_RS  66560            // sredS [64][2]
#define S3_RQ  67072            // sredQ [64][2]
#define S3_GB  67584            // gamma(64) beta(64)
#define S3_SMEM 68096

// ---------------- global scratch ----------------
__device__ float g_u[(size_t)B_ * L_ * DI_];
__device__ float g_res[(size_t)B_ * L_ * DI_];
__device__ float g_sums[NTIL * DI_];
__device__ float g_offs[NTIL * DI_];
__device__ uint4 g_xch4[(size_t)NTIL * 1024];
__device__ uint4 g_xcl4[(size_t)NTIL * 1024];
__device__ uint4 g_Bh4[4096];
__device__ uint4 g_Bl4[4096];
__device__ uint4 g_W1h4[2048];
__device__ uint4 g_W1l4[2048];
__device__ uint4 g_W3h4[1024];
__device__ uint4 g_W3l4[1024];

// ---------------- helpers ----------------
__device__ __forceinline__ float softplus_f(float v) {
    return (v > 10.f) ? v : __logf(1.f + __expf(v));
}
__device__ __forceinline__ u32 smem_u32(const void* p) {
    u32 a; asm("{ .reg .u64 t; cvta.to.shared.u64 t, %1; cvt.u32.u64 %0, t; }"
               : "=r"(a) : "l"(p));
    return a;
}
__device__ __forceinline__ void mma_bf16(float& d0, float& d1, float& d2, float& d3,
                                         u32 a0, u32 a1, u32 a2, u32 a3,
                                         u32 b0, u32 b1) {
    asm volatile("mma.sync.aligned.m16n8k16.row.col.f32.bf16.bf16.f32 "
                 "{%0,%1,%2,%3}, {%4,%5,%6,%7}, {%8,%9}, {%0,%1,%2,%3};"
                 : "+f"(d0), "+f"(d1), "+f"(d2), "+f"(d3)
                 : "r"(a0), "r"(a1), "r"(a2), "r"(a3), "r"(b0), "r"(b1));
}
__device__ __forceinline__ void ldmatrix_x4(u32& r0, u32& r1, u32& r2, u32& r3, u32 addr) {
    asm volatile("ldmatrix.sync.aligned.m8n8.x4.shared.b16 {%0,%1,%2,%3}, [%4];"
                 : "=r"(r0), "=r"(r1), "=r"(r2), "=r"(r3) : "r"(addr));
}
__device__ __forceinline__ void ldmatrix_x2t(u32& r0, u32& r1, u32 addr) {
    asm volatile("ldmatrix.sync.aligned.m8n8.x2.trans.shared.b16 {%0,%1}, [%2];"
                 : "=r"(r0), "=r"(r1) : "r"(addr));
}
#define CP_ASYNC16(dst, src) \
    asm volatile("cp.async.cg.shared.global [%0], [%1], 16;" :: "r"(dst), "l"(src))
#define CP_COMMIT() asm volatile("cp.async.commit_group;")
#define CP_WAIT(n)  asm volatile("cp.async.wait_group %0;" :: "n"(n))

__device__ __forceinline__ void bf16_split(float v, u16& h, u16& l) {
    __nv_bfloat16 hb = __float2bfloat16(v);
    __nv_bfloat16 lb = __float2bfloat16(v - __bfloat162float(hb));
    h = *reinterpret_cast<u16*>(&hb);
    l = *reinterpret_cast<u16*>(&lb);
}

// =====================================================================
// k_prep: W2, W_in, W_out -> bf16 hi/lo swizzled images
// =====================================================================
__global__ void k_prep(const float* __restrict__ W_x,
                       const float* __restrict__ W_dt,
                       const float* __restrict__ W_in,
                       const float* __restrict__ W_out)
{
    u16* bh = reinterpret_cast<u16*>(g_Bh4);
    u16* bl = reinterpret_cast<u16*>(g_Bl4);
    u16* wh = reinterpret_cast<u16*>(g_W1h4);
    u16* wl = reinterpret_cast<u16*>(g_W1l4);
    u16* oh = reinterpret_cast<u16*>(g_W3h4);
    u16* ol = reinterpret_cast<u16*>(g_W3l4);
    int idx = blockIdx.x * 256 + threadIdx.x;
    for (int i = idx; i < 128 * 256; i += gridDim.x * 256) {
        int k = i >> 8, n = i & 255;
        float w = (n < 128) ? W_x[(size_t)k * 144 + n] : W_dt[(size_t)k * 128 + (n - 128)];
        u16 h, l; bf16_split(w, h, l);
        u32 off = (u32)k * 512 + ((((n >> 3) ^ (k & 7))) << 4) + (n & 7) * 2;
        bh[off >> 1] = h; bl[off >> 1] = l;
    }
    for (int i = idx; i < 64 * 256; i += gridDim.x * 256) {
        int k = i >> 8, n = i & 255;
        float w = W_in[(size_t)k * 256 + n];
        u16 h, l; bf16_split(w, h, l);
        u32 off = (u32)k * 512 + ((((n >> 3) ^ (k & 7))) << 4) + (n & 7) * 2;
        wh[off >> 1] = h; wl[off >> 1] = l;
    }
    for (int i = idx; i < 128 * 64; i += gridDim.x * 256) {
        int k = i >> 6, n = i & 63;
        float w = W_out[(size_t)k * 64 + n];
        u16 h, l; bf16_split(w, h, l);
        u32 off = (u32)k * 128 + ((((n >> 3) ^ (k & 7))) << 4) + (n & 7) * 2;
        oh[off >> 1] = h; ol[off >> 1] = l;
    }
}

// =====================================================================
// k1a: PERSISTENT GEMM1 + conv (unchanged from R6)
// =====================================================================
__global__ __launch_bounds__(512, 1)
void k1a_kernel(const float* __restrict__ x,
                const float* __restrict__ conv_w,
                const float* __restrict__ conv_b)
{
    extern __shared__ char sm[];
    const u32 smb = smem_u32(sm);
    float* s_xs = reinterpret_cast<float*>(sm + P1_XS);

    const int tid = threadIdx.x;

    {
        uint4* dh = reinterpret_cast<uint4*>(sm + P1_W1H);
        uint4* dl = reinterpret_cast<uint4*>(sm + P1_W1L);
        for (int i = tid; i < 2048; i += 512) { dh[i] = g_W1h4[i]; dl[i] = g_W1l4[i]; }
    }
    const float cw0 = conv_w[0 * 128 + (tid & 127)];
    const float cw1 = conv_w[1 * 128 + (tid & 127)];
    const float cw2 = conv_w[2 * 128 + (tid & 127)];
    const float cw3 = conv_w[3 * 128 + (tid & 127)];
    const float cb  = conv_b[tid & 127];

    auto prefetch = [&](int tile, int buf) {
        const int b = tile / NCH;
        const int l0 = (tile - b * NCH) * 64;
        const long base = (long)b * L_ + l0 - 1;
        const u32 dst0 = smb + P1_XB + (u32)buf * 17408;
        for (int i = tid; i < 67 * 16; i += 512) {
            int r = i >> 4, q = i & 15;
            long gl = base + r;
            if (gl < 0) gl = 0;
            if (gl > (long)B_ * L_ - 1) gl = (long)B_ * L_ - 1;
            CP_ASYNC16(dst0 + (u32)(r * 64 + q * 4) * 4, x + gl * C_ + q * 4);
        }
    };

    const int tile0 = blockIdx.x;
    if (tile0 < NTIL) prefetch(tile0, 0);
    CP_COMMIT();

    int it = 0;
    for (int tile = tile0; tile < NTIL; tile += gridDim.x, it++) {
        const int buf = it & 1;
        const int b     = tile / NCH;
        const int chunk = tile - b * NCH;
        const int l0    = chunk * 64;

        const int nxt = tile + gridDim.x;
        if (nxt < NTIL) { prefetch(nxt, buf ^ 1); CP_COMMIT(); CP_WAIT(1); }
        else            { CP_WAIT(0); }
        __syncthreads();

        {
            const float* xb = reinterpret_cast<const float*>(sm + P1_XB + buf * 17408);
            for (int i = tid; i < 67 * 16; i += 512) {
                int r = i >> 4, q = i & 15;
                int l = l0 - 1 + r;
                float4 v = *reinterpret_cast<const float4*>(xb + r * 64 + q * 4);
                if (l < 0 || l >= L_) v = make_float4(0.f, 0.f, 0.f, 0.f);
                u16 h0,lo0,h1,lo1,h2,lo2,h3,lo3;
                bf16_split(v.x, h0, lo0); bf16_split(v.y, h1, lo1);
                bf16_split(v.z, h2, lo2); bf16_split(v.w, h3, lo3);
                ull hv = (ull)h0 | ((ull)h1 << 16) | ((ull)h2 << 32) | ((ull)h3 << 48);
                ull lv = (ull)lo0 | ((ull)lo1 << 16) | ((ull)lo2 << 32) | ((ull)lo3 << 48);
                u32 off = (u32)r * 128 + ((((q >> 1) ^ (r & 7))) << 4) + (q & 1) * 8;
                *reinterpret_cast<ull*>(sm + P1_A1H + off) = hv;
                *reinterpret_cast<ull*>(sm + P1_A1L + off) = lv;
            }
        }
        __syncthreads();

        {
            const int w = tid >> 5, lane = tid & 31;
            const int wm = w >> 3;
            const int wn = w & 7;

            float acc[3][4][4];
            #pragma unroll
            for (int mf = 0; mf < 3; mf++)
                #pragma unroll
                for (int nf = 0; nf < 4; nf++)
                    #pragma unroll
                    for (int j = 0; j < 4; j++) acc[mf][nf][j] = 0.f;

            const u32 aHb = smb + P1_A1H, aLb = smb + P1_A1L;
            const u32 bHb = smb + P1_W1H, bLb = smb + P1_W1L;

            #pragma unroll
            for (int ks = 0; ks < 4; ks++) {
                u32 ah[3][4], al[3][4];
                #pragma unroll
                for (int mf = 0; mf < 3; mf++) {
                    int row = wm * 48 + mf * 16 + (lane & 15);
                    int ck  = ks * 2 + (lane >> 4);
                    u32 off = (u32)row * 128 + (((ck ^ (row & 7))) << 4);
                    ldmatrix_x4(ah[mf][0], ah[mf][1], ah[mf][2], ah[mf][3], aHb + off);
                    ldmatrix_x4(al[mf][0], al[mf][1], al[mf][2], al[mf][3], aLb + off);
                }
                int krow = ks * 16 + (lane & 15);
                u32 krbase = (u32)krow * 512;
                int kx = krow & 7;
                #pragma unroll
                for (int nf = 0; nf < 4; nf++) {
                    int n0 = wn * 32 + nf * 8;
                    u32 off = krbase + ((((n0 >> 3) ^ kx)) << 4);
                    u32 bh0, bh1, bl0, bl1;
                    ldmatrix_x2t(bh0, bh1, bHb + off);
                    ldmatrix_x2t(bl0, bl1, bLb + off);
                    #pragma unroll
                    for (int mf = 0; mf < 3; mf++) {
                        mma_bf16(acc[mf][nf][0], acc[mf][nf][1], acc[mf][nf][2], acc[mf][nf][3],
                                 ah[mf][0], ah[mf][1], ah[mf][2], ah[mf][3], bh0, bh1);
                        mma_bf16(acc[mf][nf][0], acc[mf][nf][1], acc[mf][nf][2], acc[mf][nf][3],
                                 ah[mf][0], ah[mf][1], ah[mf][2], ah[mf][3], bl0, bl1);
                        mma_bf16(acc[mf][nf][0], acc[mf][nf][1], acc[mf][nf][2], acc[mf][nf][3],
                                 al[mf][0], al[mf][1], al[mf][2], al[mf][3], bh0, bh1);
                    }
                }
            }

            #pragma unroll
            for (int mf = 0; mf < 3; mf++) {
                const int r0 = wm * 48 + mf * 16 + (lane >> 2);
                #pragma unroll
                for (int nf = 0; nf < 4; nf++) {
                    const int n = wn * 32 + nf * 8 + (lane & 3) * 2;
                    if (wn < 4) {
                        if (r0 < 67)
                            *reinterpret_cast<float2*>(s_xs + r0 * 130 + n) =
                                make_float2(acc[mf][nf][0], acc[mf][nf][1]);
                        if (r0 + 8 < 67)
                            *reinterpret_cast<float2*>(s_xs + (r0 + 8) * 130 + n) =
                                make_float2(acc[mf][nf][2], acc[mf][nf][3]);
                    } else {
                        const int nn = n - 128;
                        if (r0 >= 1 && r0 <= 64) {
                            float v0 = acc[mf][nf][0], v1 = acc[mf][nf][1];
                            *reinterpret_cast<float2*>(
                                g_res + ((size_t)b * L_ + l0 + r0 - 1) * DI_ + nn) =
                                make_float2(v0 / (1.f + __expf(-v0)), v1 / (1.f + __expf(-v1)));
                        }
                        const int r1 = r0 + 8;
                        if (r1 >= 1 && r1 <= 64) {
                            float v0 = acc[mf][nf][2], v1 = acc[mf][nf][3];
                            *reinterpret_cast<float2*>(
                                g_res + ((size_t)b * L_ + l0 + r1 - 1) * DI_ + nn) =
                                make_float2(v0 / (1.f + __expf(-v0)), v1 / (1.f + __expf(-v1)));
                        }
                    }
                }
            }
        }
        __syncthreads();

        {
            u16* imgh = reinterpret_cast<u16*>(sm + P1_XCH);
            u16* imgl = reinterpret_cast<u16*>(sm + P1_XCL);
            const int cch = tid & 127, qtr = tid >> 7;
            const int t0 = qtr * 16;
            float v0 = s_xs[(t0 + 0) * 130 + cch];
            float v1 = s_xs[(t0 + 1) * 130 + cch];
            float v2 = s_xs[(t0 + 2) * 130 + cch];
            #pragma unroll 4
            for (int t = t0; t < t0 + 16; t++) {
                float v3 = s_xs[(t + 3) * 130 + cch];
                float z = fmaf(cw0, v0, fmaf(cw1, v1, fmaf(cw2, v2, fmaf(cw3, v3, cb))));
                float sig = 1.f / (1.f + __expf(-z));
                float v = z * sig;
                u16 h, l; bf16_split(v, h, l);
                u32 off = (u32)t * 256 + ((((cch >> 3) ^ (t & 7))) << 4) + (cch & 7) * 2;
                imgh[off >> 1] = h; imgl[off >> 1] = l;
                v0 = v1; v1 = v2; v2 = v3;
            }
        }
        __syncthreads();

        {
            const uint4* sh = reinterpret_cast<const uint4*>(sm + P1_XCH);
            const uint4* sl = reinterpret_cast<const uint4*>(sm + P1_XCL);
            for (int i = tid; i < 1024; i += 512) {
                g_xch4[(size_t)tile * 1024 + i] = sh[i];
                g_xcl4[(size_t)tile * 1024 + i] = sl[i];
            }
        }
        __syncthreads();
    }
}

// =====================================================================
// kb: persistent tensor GEMM2, 512 threads (16 warps = 4M x 4N)
// =====================================================================
__global__ __launch_bounds__(512, 1)
void kb_kernel(const float* __restrict__ b_dt)
{
    extern __shared__ char sm[];
    const u32 smb = smem_u32(sm);
    float* s_bdt  = reinterpret_cast<float*>(sm + KB_BDT);
    float* s_sums = reinterpret_cast<float*>(sm + KB_SUMS);

    const int tid  = threadIdx.x;
    const int w    = tid >> 5;
    const int lane = tid & 31;
    const int wm   = w >> 2;        // 0..3 : M rows [wm*16, +16)
    const int wn   = w & 3;         // 0..3 : xp cols [wn*32, +32), dt +128

    {
        uint4* dh = reinterpret_cast<uint4*>(sm + KB_BH);
        uint4* dl = reinterpret_cast<uint4*>(sm + KB_BL);
        for (int i = tid; i < 4096; i += 512) { dh[i] = g_Bh4[i]; dl[i] = g_Bl4[i]; }
    }
    if (tid < 128) { s_bdt[tid] = b_dt[tid]; s_sums[tid] = 0.f; }

    int tile0 = blockIdx.x;
    if (tile0 < NTIL) {
        u32 dh = smb + KB_A;
        const char* srcH = reinterpret_cast<const char*>(g_xch4 + (size_t)tile0 * 1024);
        const char* srcL = reinterpret_cast<const char*>(g_xcl4 + (size_t)tile0 * 1024);
        for (int i = tid; i < 1024; i += 512) {
            CP_ASYNC16(dh + i * 16,         srcH + i * 16);
            CP_ASYNC16(dh + 16384 + i * 16, srcL + i * 16);
        }
    }
    CP_COMMIT();

    int it = 0;
    for (int tile = tile0; tile < NTIL; tile += gridDim.x, it++) {
        const int buf = it & 1;
        const int nxt = tile + gridDim.x;
        if (nxt < NTIL) {
            u32 dh = smb + KB_A + (buf ^ 1) * 32768;
            const char* srcH = reinterpret_cast<const char*>(g_xch4 + (size_t)nxt * 1024);
            const char* srcL = reinterpret_cast<const char*>(g_xcl4 + (size_t)nxt * 1024);
            for (int i = tid; i < 1024; i += 512) {
                CP_ASYNC16(dh + i * 16,         srcH + i * 16);
                CP_ASYNC16(dh + 16384 + i * 16, srcL + i * 16);
            }
            CP_COMMIT();
            CP_WAIT(1);
        } else {
            CP_WAIT(0);
        }
        __syncthreads();

        const u32 aH = smb + KB_A + buf * 32768;
        const u32 aL = aH + 16384;
        const u32 bH = smb + KB_BH;
        const u32 bL = smb + KB_BL;

        float acc[8][4];
        #pragma unroll
        for (int nf = 0; nf < 8; nf++)
            #pragma unroll
            for (int j = 0; j < 4; j++) acc[nf][j] = 0.f;

        #pragma unroll 1
        for (int ks = 0; ks < 8; ks++) {
            u32 ah[4], al[4];
            {
                int row = wm * 16 + (lane & 15);
                int ck = ks * 2 + (lane >> 4);
                u32 off = (u32)row * 256 + (((ck ^ (row & 7))) << 4);
                ldmatrix_x4(ah[0], ah[1], ah[2], ah[3], aH + off);
                ldmatrix_x4(al[0], al[1], al[2], al[3], aL + off);
            }
            int krow = ks * 16 + (lane & 15);
            u32 krbase = (u32)krow * 512;
            int kx = krow & 7;
            #pragma unroll
            for (int nfi = 0; nfi < 8; nfi++) {
                int n0 = (nfi < 4) ? (wn * 32 + nfi * 8) : (128 + wn * 32 + (nfi - 4) * 8);
                u32 off = krbase + ((((n0 >> 3) ^ kx)) << 4);
                u32 bh0, bh1, bl0, bl1;
                ldmatrix_x2t(bh0, bh1, bH + off);
                ldmatrix_x2t(bl0, bl1, bL + off);
                mma_bf16(acc[nfi][0], acc[nfi][1], acc[nfi][2], acc[nfi][3],
                         ah[0], ah[1], ah[2], ah[3], bh0, bh1);
                mma_bf16(acc[nfi][0], acc[nfi][1], acc[nfi][2], acc[nfi][3],
                         ah[0], ah[1], ah[2], ah[3], bl0, bl1);
                mma_bf16(acc[nfi][0], acc[nfi][1], acc[nfi][2], acc[nfi][3],
                         al[0], al[1], al[2], al[3], bh0, bh1);
            }
        }

        {
            const int r0 = wm * 16 + (lane >> 2);
            const size_t tok0 = (size_t)tile * 64 + r0;
            #pragma unroll
            for (int nfi = 0; nfi < 4; nfi++) {
                const int n = wn * 32 + nfi * 8 + (lane & 3) * 2;
                float bd0 = s_bdt[n], bd1 = s_bdt[n + 1];
                float u00 = acc[nfi][0] * softplus_f(acc[nfi + 4][0] + bd0);
                float u01 = acc[nfi][1] * softplus_f(acc[nfi + 4][1] + bd1);
                float u10 = acc[nfi][2] * softplus_f(acc[nfi + 4][2] + bd0);
                float u11 = acc[nfi][3] * softplus_f(acc[nfi + 4][3] + bd1);
                *reinterpret_cast<float2*>(g_u + tok0 * DI_ + n)       = make_float2(u00, u01);
                *reinterpret_cast<float2*>(g_u + (tok0 + 8) * DI_ + n) = make_float2(u10, u11);
                float p0 = u00 + u10, p1 = u01 + u11;
                #pragma unroll
                for (int m = 4; m <= 16; m <<= 1) {
                    p0 += __shfl_xor_sync(0xffffffffu, p0, m);
                    p1 += __shfl_xor_sync(0xffffffffu, p1, m);
                }
                if ((lane >> 2) == 0) {
                    atomicAdd(&s_sums[n], p0);
                    atomicAdd(&s_sums[n + 1], p1);
                }
            }
        }
        __syncthreads();
        if (tid < 128) {
            g_sums[(size_t)tile * DI_ + tid] = s_sums[tid];
            s_sums[tid] = 0.f;
        }
    }
}

// =====================================================================
// K2: exclusive scan of chunk sums
// =====================================================================
__global__ void k2_scan(void)
{
    const int b = blockIdx.x >> 7;
    const int c = blockIdx.x & 127;
    const int t = threadIdx.x;
    __shared__ float part[64];

    float local[27];
    float s = 0.f;
    #pragma unroll
    for (int i = 0; i < 27; i++) {
        local[i] = g_sums[(b * NCH + t * 27 + i) * DI_ + c];
        s += local[i];
    }
    part[t] = s;
    __syncthreads();
    if (t == 0) {
        float run = 0.f;
        for (int i = 0; i < 64; i++) { float v = part[i]; part[i] = run; run += v; }
    }
    __syncthreads();
    float run = part[t];
    #pragma unroll
    for (int i = 0; i < 27; i++) {
        g_offs[(b * NCH + t * 27 + i) * DI_ + c] = run;
        run += local[i];
    }
}

// =====================================================================
// K3: in-chunk scan -> y (bf16 hi/lo images) ; tensor y@W_out ; +x ; LN
// =====================================================================
__global__ __launch_bounds__(256, 3)
void k3_kernel(const float* __restrict__ x,
               const float* __restrict__ gamma,
               const float* __restrict__ beta,
               float* __restrict__ out)
{
    extern __shared__ char sm[];
    const u32 smb = smem_u32(sm);
    float* s_off = reinterpret_cast<float*>(sm + S3_OFF);
    float* s_mid = reinterpret_cast<float*>(sm + S3_MID);
    float* s_rs  = reinterpret_cast<float*>(sm + S3_RS);   // [64][2]
    float* s_rq  = reinterpret_cast<float*>(sm + S3_RQ);   // [64][2]
    float* s_gb  = reinterpret_cast<float*>(sm + S3_GB);   // gamma 64 | beta 64

    const int bc    = blockIdx.x;
    const int b     = bc / NCH;
    const int chunk = bc - b * NCH;
    const int l0    = chunk * 64;
    const int tid   = threadIdx.x;

    // stage W_out images + gamma/beta + offsets
    {
        uint4* dh = reinterpret_cast<uint4*>(sm + S3_W3H);
        uint4* dl = reinterpret_cast<uint4*>(sm + S3_W3L);
        for (int i = tid; i < 1024; i += 256) { dh[i] = g_W3h4[i]; dl[i] = g_W3l4[i]; }
    }
    if (tid < 64)  s_gb[tid] = gamma[tid];
    else if (tid < 128) s_gb[tid] = beta[tid - 64];
    if (tid < 128) s_off[tid] = g_offs[(b * NCH + chunk) * DI_ + tid];
    __syncthreads();

    // ---- phase A: split-half scan, y -> bf16 hi/lo images ----
    {
        u16* imgYH = reinterpret_cast<u16*>(sm + S3_YH);
        u16* imgYL = reinterpret_cast<u16*>(sm + S3_YL);
        const int c = tid & 127, h = tid >> 7;
        const size_t base = ((size_t)b * L_ + l0 + h * 32) * DI_ + c;
        float uv[32];
        #pragma unroll
        for (int i = 0; i < 32; i++) uv[i] = g_u[base + (size_t)i * DI_];
        float ps = 0.f;
        #pragma unroll
        for (int i = 0; i < 32; i++) ps += uv[i];
        if (h == 0) s_mid[c] = ps;
        __syncthreads();
        float run = s_off[c] + (h ? s_mid[c] : 0.f);
        #pragma unroll
        for (int i = 0; i < 32; i++) {
            run += uv[i];
            float r = g_res[base + (size_t)i * DI_];
            float y = run * r;
            u16 hh, ll; bf16_split(y, hh, ll);
            int t = h * 32 + i;
            u32 off = (u32)t * 256 + ((((c >> 3) ^ (t & 7))) << 4) + (c & 7) * 2;
            imgYH[off >> 1] = hh;
            imgYL[off >> 1] = ll;
        }
    }
    __syncthreads();

    // ---- phase B: y[64x128] @ W_out[128x64] via split-bf16 mma ----
    {
        const int w = tid >> 5, lane = tid & 31;
        const int wm = w >> 1;          // 0..3 : rows wm*16
        const int wn = w & 1;           // 0..1 : cols wn*32

        float acc[4][4];
        #pragma unroll
        for (int nf = 0; nf < 4; nf++)
            #pragma unroll
            for (int j = 0; j < 4; j++) acc[nf][j] = 0.f;

        const u32 yHb = smb + S3_YH, yLb = smb + S3_YL;
        const u32 wHb = smb + S3_W3H, wLb = smb + S3_W3L;

        #pragma unroll
        for (int ks = 0; ks < 8; ks++) {
            u32 ah[4], al[4];
            {
                int row = wm * 16 + (lane & 15);
                int ck = ks * 2 + (lane >> 4);
                u32 off = (u32)row * 256 + (((ck ^ (row & 7))) << 4);
                ldmatrix_x4(ah[0], ah[1], ah[2], ah[3], yHb + off);
                ldmatrix_x4(al[0], al[1], al[2], al[3], yLb + off);
            }
            int krow = ks * 16 + (lane & 15);
            u32 krbase = (u32)krow * 128;
            int kx = krow & 7;
            #pragma unroll
            for (int nf = 0; nf < 4; nf++) {
                int n0 = wn * 32 + nf * 8;
                u32 off = krbase + ((((n0 >> 3) ^ kx)) << 4);
                u32 bh0, bh1, bl0, bl1;
                ldmatrix_x2t(bh0, bh1, wHb + off);
                ldmatrix_x2t(bl0, bl1, wLb + off);
                mma_bf16(acc[nf][0], acc[nf][1], acc[nf][2], acc[nf][3],
                         ah[0], ah[1], ah[2], ah[3], bh0, bh1);
                mma_bf16(acc[nf][0], acc[nf][1], acc[nf][2], acc[nf][3],
                         ah[0], ah[1], ah[2], ah[3], bl0, bl1);
                mma_bf16(acc[nf][0], acc[nf][1], acc[nf][2], acc[nf][3],
                         al[0], al[1], al[2], al[3], bh0, bh1);
            }
        }

        // +x, partial LN sums
        const int r0 = wm * 16 + (lane >> 2);
        const int r1 = r0 + 8;
        float z[4][4];
        float s0 = 0.f, q0 = 0.f, s1 = 0.f, q1 = 0.f;
        #pragma unroll
        for (int nf = 0; nf < 4; nf++) {
            const int c0 = wn * 32 + nf * 8 + (lane & 3) * 2;
            float2 x0 = *reinterpret_cast<const float2*>(x + ((size_t)b * L_ + l0 + r0) * C_ + c0);
            float2 x1 = *reinterpret_cast<const float2*>(x + ((size_t)b * L_ + l0 + r1) * C_ + c0);
            z[nf][0] = acc[nf][0] + x0.x;
            z[nf][1] = acc[nf][1] + x0.y;
            z[nf][2] = acc[nf][2] + x1.x;
            z[nf][3] = acc[nf][3] + x1.y;
            s0 += z[nf][0] + z[nf][1];
            q0 += z[nf][0] * z[nf][0] + z[nf][1] * z[nf][1];
            s1 += z[nf][2] + z[nf][3];
            q1 += z[nf][2] * z[nf][2] + z[nf][3] * z[nf][3];
        }
        #pragma unroll
        for (int m = 1; m <= 2; m <<= 1) {
            s0 += __shfl_xor_sync(0xffffffffu, s0, m);
            q0 += __shfl_xor_sync(0xffffffffu, q0, m);
            s1 += __shfl_xor_sync(0xffffffffu, s1, m);
            q1 += __shfl_xor_sync(0xffffffffu, q1, m);
        }
        if ((lane & 3) == 0) {
            s_rs[r0 * 2 + wn] = s0; s_rq[r0 * 2 + wn] = q0;
            s_rs[r1 * 2 + wn] = s1; s_rq[r1 * 2 + wn] = q1;
        }
        __syncthreads();

        float su0 = s_rs[r0 * 2] + s_rs[r0 * 2 + 1];
        float qu0 = s_rq[r0 * 2] + s_rq[r0 * 2 + 1];
        float su1 = s_rs[r1 * 2] + s_rs[r1 * 2 + 1];
        float qu1 = s_rq[r1 * 2] + s_rq[r1 * 2 + 1];
        float mu0 = su0 * (1.f / 64.f);
        float inv0 = rsqrtf(qu0 * (1.f / 64.f) - mu0 * mu0 + EPS_);
        float mu1 = su1 * (1.f / 64.f);
        float inv1 = rsqrtf(qu1 * (1.f / 64.f) - mu1 * mu1 + EPS_);

        #pragma unroll
        for (int nf = 0; nf < 4; nf++) {
            const int c0 = wn * 32 + nf * 8 + (lane & 3) * 2;
            float g0 = s_gb[c0], g1 = s_gb[c0 + 1];
            float be0 = s_gb[64 + c0], be1 = s_gb[64 + c0 + 1];
            *reinterpret_cast<float2*>(out + ((size_t)b * L_ + l0 + r0) * C_ + c0) =
                make_float2(fmaf(g0, (z[nf][0] - mu0) * inv0, be0),
                            fmaf(g1, (z[nf][1] - mu0) * inv0, be1));
            *reinterpret_cast<float2*>(out + ((size_t)b * L_ + l0 + r1) * C_ + c0) =
                make_float2(fmaf(g0, (z[nf][2] - mu1) * inv1, be0),
                            fmaf(g1, (z[nf][3] - mu1) * inv1, be1));
        }
    }
}

// =====================================================================
extern "C" void kernel_launch(void* const* d_in, const int* in_sizes, int n_in,
                              void* d_out, int out_size)
{
    (void)in_sizes; (void)n_in; (void)out_size;
    const float* x      = (const float*)d_in[0];
    const float* W_in   = (const float*)d_in[1];
    const float* conv_w = (const float*)d_in[2];
    const float* conv_b = (const float*)d_in[3];
    const float* W_x    = (const float*)d_in[4];
    const float* W_dt   = (const float*)d_in[5];
    const float* b_dt   = (const float*)d_in[6];
    const float* W_out  = (const float*)d_in[7];
    const float* gamma  = (const float*)d_in[8];
    const float* beta   = (const float*)d_in[9];
    float* out = (float*)d_out;

    cudaFuncSetAttribute(k1a_kernel, cudaFuncAttributeMaxDynamicSharedMemorySize, P1_SMEM);
    cudaFuncSetAttribute(kb_kernel,  cudaFuncAttributeMaxDynamicSharedMemorySize, KB_SMEM);
    cudaFuncSetAttribute(k3_kernel,  cudaFuncAttributeMaxDynamicSharedMemorySize, S3_SMEM);

    k_prep<<<16, 256>>>(W_x, W_dt, W_in, W_out);
    k1a_kernel<<<148, 512, P1_SMEM>>>(x, conv_w, conv_b);
    kb_kernel<<<148, 512, KB_SMEM>>>(b_dt);
    k2_scan<<<B_ * 128, 64>>>();
    k3_kernel<<<NTIL, 256, S3_SMEM>>>(x, gamma, beta, out);
}